// round 1
// baseline (speedup 1.0000x reference)
#include <cuda_runtime.h>

#define B_ 4
#define C_ 64
#define N_ 8192
#define K_ 32
#define R2_ 0.04f
#define BN_EPS_ 1e-5f
#define QPB 2   // queries per block in aggregation

// Scratch (static __device__ arrays — no allocation)
__device__ float g_sq[B_ * N_];
__device__ float g_feaT[B_ * N_ * C_];   // (B, N, C) transposed features
__device__ int   g_gidx[B_ * N_ * K_];   // final (masked) neighbor indices

// ---------------------------------------------------------------------------
// Prep: squared norms (exact same FMA chain as the KNN dot product so that
// self-distance computes to exactly 0) + feature transpose (B,C,N)->(B,N,C)
// ---------------------------------------------------------------------------
__global__ void prep_kernel(const float* __restrict__ coor,
                            const float* __restrict__ fea) {
    int id = blockIdx.x * blockDim.x + threadIdx.x;
    if (id < B_ * N_) {
        int b = id / N_, n = id % N_;
        const float* cb = coor + b * 3 * N_;
        float x = cb[n], y = cb[N_ + n], z = cb[2 * N_ + n];
        g_sq[id] = fmaf(x, x, fmaf(y, y, z * z));
    }
    int total = B_ * C_ * N_;
    int stride = gridDim.x * blockDim.x;
    for (int e = id; e < total; e += stride) {
        int b = e / (C_ * N_);
        int r = e % (C_ * N_);
        int c = r / N_;
        int n = r % N_;
        g_feaT[(b * N_ + n) * C_ + c] = fea[e];
    }
}

// ---------------------------------------------------------------------------
// KNN: one warp per query. Distributed top-32 heap: one (dist, idx) slot per
// lane. Candidates pruned at R^2 (ball-query mask means far neighbors are
// replaced by self anyway). Insert via redux-max + ballot + shfl.
// ---------------------------------------------------------------------------
__global__ __launch_bounds__(256) void knn_kernel(const float* __restrict__ coor) {
    __shared__ float4 tile[1024];
    const int b    = blockIdx.y;
    const int warp = threadIdx.x >> 5;
    const int lane = threadIdx.x & 31;
    const int q    = blockIdx.x * 8 + warp;

    const float* cb = coor + b * 3 * N_;
    const float qx  = cb[q];
    const float qy  = cb[N_ + q];
    const float qz  = cb[2 * N_ + q];
    const float qsq = g_sq[b * N_ + q];

    float myd    = __int_as_float(0x7f800000);  // +inf
    int   myidx  = 0;
    float curmax = myd;
    int   maxlane = 0;

    for (int tbase = 0; tbase < N_; tbase += 1024) {
        __syncthreads();
#pragma unroll
        for (int i = 0; i < 4; i++) {
            int j = threadIdx.x + i * 256;
            int n = tbase + j;
            tile[j] = make_float4(cb[n], cb[N_ + n], cb[2 * N_ + n], g_sq[b * N_ + n]);
        }
        __syncthreads();
        for (int s = 0; s < 32; s++) {
            float4 c4 = tile[s * 32 + lane];
            float dot = fmaf(qx, c4.x, fmaf(qy, c4.y, qz * c4.z));
            float d   = fmaf(-2.f, dot, qsq + c4.w);
            d = fmaxf(d, 0.f);  // keep float-as-uint compare monotonic
            int cidx = tbase + s * 32 + lane;
            bool ok = (d <= R2_) && (d < curmax);
            unsigned mask = __ballot_sync(0xffffffffu, ok);
            while (mask) {
                int j2 = __ffs(mask) - 1;
                mask &= mask - 1;
                float dj = __shfl_sync(0xffffffffu, d, j2);
                int   cj = __shfl_sync(0xffffffffu, cidx, j2);
                if (dj < curmax) {  // warp-uniform
                    if (lane == maxlane) { myd = dj; myidx = cj; }
                    unsigned cm = __reduce_max_sync(0xffffffffu, __float_as_uint(myd));
                    curmax  = __uint_as_float(cm);
                    maxlane = __ffs(__ballot_sync(0xffffffffu,
                                        __float_as_uint(myd) == cm)) - 1;
                }
            }
        }
    }
    // Slots that never got a within-radius neighbor (incl. padding) -> self,
    // matching the reference's mask with group_idx[:, :, :1] (= self, d==0).
    int finalIdx = (myd <= R2_) ? myidx : q;
    g_gidx[(b * N_ + q) * K_ + lane] = finalIdx;
}

// ---------------------------------------------------------------------------
// Aggregation: per query gather K=32 neighbors' [fea(64) | (xyz-c)/R (3) | 0]
// into shared (68-wide padded rows), GEMM against BN-folded W held in
// registers (17 x float4 per thread), ReLU+max over K, transposed store.
// ---------------------------------------------------------------------------
__global__ __launch_bounds__(128, 4) void agg_kernel(
    const float* __restrict__ coor,
    const float* __restrict__ W,
    const float* __restrict__ gamma_, const float* __restrict__ beta_,
    const float* __restrict__ rmean, const float* __restrict__ rvar,
    float* __restrict__ out)
{
    __shared__ __align__(16) float Ws[64 * 68];
    __shared__ __align__(16) float gs[QPB * 32 * 68];
    __shared__ int   sIdx[QPB * 32];
    __shared__ float outs[QPB * 64];

    const int b   = blockIdx.y;
    const int q0  = blockIdx.x * QPB;
    const int tid = threadIdx.x;
    const int ql  = tid >> 6;      // local query 0..QPB-1
    const int d   = tid & 63;      // output channel

    // Stage W (coalesced) into padded shared
    for (int e = tid; e < 64 * 67; e += 128) {
        int r = e / 67, c = e % 67;
        Ws[r * 68 + c] = W[e];
    }
    if (tid < 64) Ws[tid * 68 + 67] = 0.f;
    // Neighbor indices
    for (int e = tid; e < QPB * 32; e += 128) {
        sIdx[e] = g_gidx[(b * N_ + q0 + (e >> 5)) * K_ + (e & 31)];
    }
    __syncthreads();

    // Per-thread BN-folded weight row in registers
    float scale = gamma_[d] / sqrtf(rvar[d] + BN_EPS_);
    float bias  = beta_[d] - rmean[d] * scale;
    float4 wr[17];
#pragma unroll
    for (int i = 0; i < 17; i++) {
        float4 w4 = *reinterpret_cast<const float4*>(&Ws[d * 68 + 4 * i]);
        w4.x *= scale; w4.y *= scale; w4.z *= scale; w4.w *= scale;
        wr[i] = w4;
    }

    // Stage gathered g rows (coalesced: feaT rows are contiguous in c)
    const float* cb = coor + b * 3 * N_;
    for (int e = tid; e < QPB * 32 * 68; e += 128) {
        int q = e / (32 * 68);
        int r = e % (32 * 68);
        int k = r / 68;
        int c = r % 68;
        int id = sIdx[q * 32 + k];
        float v;
        if (c < 64) {
            v = g_feaT[(b * N_ + id) * 64 + c];
        } else if (c < 67) {
            int ax = c - 64;
            v = (cb[ax * N_ + id] - cb[ax * N_ + q0 + q]) * 5.0f;  // /RADIUS
        } else {
            v = 0.f;
        }
        gs[e] = v;
    }
    __syncthreads();

    const float4* gq = reinterpret_cast<const float4*>(&gs[ql * 32 * 68]);
    float omax = 0.f;  // relu(y) >= 0, so 0 is the identity for the max
#pragma unroll 4
    for (int k = 0; k < 32; k++) {
        const float4* gk = gq + k * 17;
        float a0 = 0.f, a1 = 0.f, a2 = 0.f, a3 = 0.f;
#pragma unroll
        for (int i = 0; i < 17; i++) {
            float4 g4 = gk[i];  // warp-broadcast LDS.128
            a0 = fmaf(g4.x, wr[i].x, a0);
            a1 = fmaf(g4.y, wr[i].y, a1);
            a2 = fmaf(g4.z, wr[i].z, a2);
            a3 = fmaf(g4.w, wr[i].w, a3);
        }
        float y = (a0 + a1) + (a2 + a3) + bias;
        omax = fmaxf(omax, y);
    }
    outs[ql * 64 + d] = omax;
    __syncthreads();

    // Transposed store: out[b][d][n], contiguous q within each row
    int d2 = tid >> 1, q2 = tid & 1;
    out[(b * 64 + d2) * N_ + q0 + q2] = outs[q2 * 64 + d2];
}

// ---------------------------------------------------------------------------
extern "C" void kernel_launch(void* const* d_in, const int* in_sizes, int n_in,
                              void* d_out, int out_size) {
    const float* coor  = (const float*)d_in[0];
    const float* fea   = (const float*)d_in[1];
    const float* W     = (const float*)d_in[2];
    const float* gamma = (const float*)d_in[3];
    const float* beta  = (const float*)d_in[4];
    const float* rmean = (const float*)d_in[5];
    const float* rvar  = (const float*)d_in[6];
    float* out = (float*)d_out;

    prep_kernel<<<256, 256>>>(coor, fea);
    knn_kernel<<<dim3(N_ / 8, B_), 256>>>(coor);
    agg_kernel<<<dim3(N_ / QPB, B_), 128>>>(coor, W, gamma, beta, rmean, rvar, out);
}

// round 2
// speedup vs baseline: 1.0870x; 1.0870x over previous
#include <cuda_runtime.h>

#define B_ 4
#define C_ 64
#define N_ 8192
#define K_ 32
#define R2_ 0.04f
#define BN_EPS_ 1e-5f
#define QPB 2   // queries per block in aggregation

// Scratch (static __device__ arrays — no allocation)
__device__ float g_feaT[B_ * N_ * C_];   // (B, N, C) transposed features
__device__ int   g_gidx[B_ * N_ * K_];   // final (masked) neighbor indices

// ---------------------------------------------------------------------------
// KNN: one warp per query. Distributed top-32 heap: one (dist, idx) slot per
// lane. Candidates pruned at R^2 (ball-query mask means far neighbors are
// replaced by self anyway). Insert via redux-max + ballot + shfl.
// Prologue also performs the (B,C,N)->(B,N,C) feature transpose (was a
// separate prep kernel) and sq-norms are computed in-tile with the exact
// same fmaf chain so self-distance is exactly 0.
// ---------------------------------------------------------------------------
__global__ __launch_bounds__(256) void knn_kernel(const float* __restrict__ coor,
                                                  const float* __restrict__ fea) {
    // ---- fused feature transpose (coalesced reads, strided writes) ----
    {
        int gid = (blockIdx.y * gridDim.x + blockIdx.x) * blockDim.x + threadIdx.x;
        int gstride = gridDim.x * gridDim.y * blockDim.x;
        for (int e = gid; e < B_ * C_ * N_; e += gstride) {
            int b = e / (C_ * N_);
            int r = e % (C_ * N_);
            int c = r / N_;
            int n = r % N_;
            g_feaT[(b * N_ + n) * C_ + c] = fea[e];
        }
    }

    __shared__ float4 tile[1024];
    const int b    = blockIdx.y;
    const int warp = threadIdx.x >> 5;
    const int lane = threadIdx.x & 31;
    const int q    = blockIdx.x * 8 + warp;

    const float* cb = coor + b * 3 * N_;
    const float qx  = cb[q];
    const float qy  = cb[N_ + q];
    const float qz  = cb[2 * N_ + q];
    const float qsq = fmaf(qx, qx, fmaf(qy, qy, qz * qz));

    float myd    = __int_as_float(0x7f800000);  // +inf
    int   myidx  = 0;
    float curmax = myd;
    int   maxlane = 0;

    for (int tbase = 0; tbase < N_; tbase += 1024) {
        __syncthreads();
#pragma unroll
        for (int i = 0; i < 4; i++) {
            int j = threadIdx.x + i * 256;
            int n = tbase + j;
            float x = cb[n], y = cb[N_ + n], z = cb[2 * N_ + n];
            tile[j] = make_float4(x, y, z, fmaf(x, x, fmaf(y, y, z * z)));
        }
        __syncthreads();
#pragma unroll 4
        for (int s = 0; s < 32; s++) {
            float4 c4 = tile[s * 32 + lane];
            float dot = fmaf(qx, c4.x, fmaf(qy, c4.y, qz * c4.z));
            float d   = fmaf(-2.f, dot, qsq + c4.w);
            d = fmaxf(d, 0.f);  // keep float-as-uint compare monotonic
            int cidx = tbase + s * 32 + lane;
            bool ok = (d <= R2_) && (d < curmax);
            unsigned mask = __ballot_sync(0xffffffffu, ok);
            while (mask) {
                int j2 = __ffs(mask) - 1;
                mask &= mask - 1;
                float dj = __shfl_sync(0xffffffffu, d, j2);
                int   cj = __shfl_sync(0xffffffffu, cidx, j2);
                if (dj < curmax) {  // warp-uniform
                    if (lane == maxlane) { myd = dj; myidx = cj; }
                    unsigned cm = __reduce_max_sync(0xffffffffu, __float_as_uint(myd));
                    curmax  = __uint_as_float(cm);
                    maxlane = __ffs(__ballot_sync(0xffffffffu,
                                        __float_as_uint(myd) == cm)) - 1;
                }
            }
        }
    }
    // Slots that never got a within-radius neighbor (incl. padding) -> self,
    // matching the reference's mask with group_idx[:, :, :1] (= self, d==0).
    int finalIdx = (myd <= R2_) ? myidx : q;
    g_gidx[(b * N_ + q) * K_ + lane] = finalIdx;
}

// ---------------------------------------------------------------------------
// Aggregation: per query gather K=32 neighbors' [fea(64) | (xyz-c)/R (3) | 0]
// into shared (68-wide padded rows), GEMM against BN-folded W held in
// registers as packed f32x2 pairs (fma.rn.f32x2 = 2 bitwise-exact fp32 FMAs
// per instruction), ReLU+max over K, transposed store.
// ---------------------------------------------------------------------------
__global__ __launch_bounds__(128, 4) void agg_kernel(
    const float* __restrict__ coor,
    const float* __restrict__ W,
    const float* __restrict__ gamma_, const float* __restrict__ beta_,
    const float* __restrict__ rmean, const float* __restrict__ rvar,
    float* __restrict__ out)
{
    __shared__ __align__(16) float Ws[64 * 68];
    __shared__ __align__(16) float gs[QPB * 32 * 68];
    __shared__ int   sIdx[QPB * 32];
    __shared__ float outs[QPB * 64];

    const int b   = blockIdx.y;
    const int q0  = blockIdx.x * QPB;
    const int tid = threadIdx.x;
    const int ql  = tid >> 6;      // local query 0..QPB-1
    const int d   = tid & 63;      // output channel

    // Stage W (coalesced) into padded shared
    for (int e = tid; e < 64 * 67; e += 128) {
        int r = e / 67, c = e % 67;
        Ws[r * 68 + c] = W[e];
    }
    if (tid < 64) Ws[tid * 68 + 67] = 0.f;
    // Neighbor indices
    for (int e = tid; e < QPB * 32; e += 128) {
        sIdx[e] = g_gidx[(b * N_ + q0 + (e >> 5)) * K_ + (e & 31)];
    }
    __syncthreads();

    // Per-thread BN-folded weight row in registers, packed as f32x2 pairs
    float scale = gamma_[d] / sqrtf(rvar[d] + BN_EPS_);
    float bias  = beta_[d] - rmean[d] * scale;
    unsigned long long w01[17], w23[17];
#pragma unroll
    for (int i = 0; i < 17; i++) {
        float4 w4 = *reinterpret_cast<const float4*>(&Ws[d * 68 + 4 * i]);
        float2 p0 = make_float2(w4.x * scale, w4.y * scale);
        float2 p1 = make_float2(w4.z * scale, w4.w * scale);
        w01[i] = *reinterpret_cast<unsigned long long*>(&p0);
        w23[i] = *reinterpret_cast<unsigned long long*>(&p1);
    }

    // Stage gathered g rows (coalesced: feaT rows are contiguous in c)
    const float* cb = coor + b * 3 * N_;
    for (int e = tid; e < QPB * 32 * 68; e += 128) {
        int q = e / (32 * 68);
        int r = e % (32 * 68);
        int k = r / 68;
        int c = r % 68;
        int id = sIdx[q * 32 + k];
        float v;
        if (c < 64) {
            v = g_feaT[(b * N_ + id) * 64 + c];
        } else if (c < 67) {
            int ax = c - 64;
            v = (cb[ax * N_ + id] - cb[ax * N_ + q0 + q]) * 5.0f;  // /RADIUS
        } else {
            v = 0.f;
        }
        gs[e] = v;
    }
    __syncthreads();

    const ulonglong2* gq = reinterpret_cast<const ulonglong2*>(&gs[ql * 32 * 68]);
    float omax = 0.f;  // relu(y) >= 0, so 0 is the identity for the max
#pragma unroll 2
    for (int k = 0; k < 32; k++) {
        const ulonglong2* gk = gq + k * 17;
        unsigned long long acc01 = 0ull;  // = (0.0f, 0.0f)
        unsigned long long acc23 = 0ull;
#pragma unroll
        for (int i = 0; i < 17; i++) {
            ulonglong2 g2 = gk[i];  // ld.shared.v2.u64 (warp-broadcast LDS.128)
            asm("fma.rn.f32x2 %0, %1, %2, %0;" : "+l"(acc01) : "l"(g2.x), "l"(w01[i]));
            asm("fma.rn.f32x2 %0, %1, %2, %0;" : "+l"(acc23) : "l"(g2.y), "l"(w23[i]));
        }
        float a0 = __uint_as_float((unsigned)(acc01 & 0xffffffffull));
        float a1 = __uint_as_float((unsigned)(acc01 >> 32));
        float a2 = __uint_as_float((unsigned)(acc23 & 0xffffffffull));
        float a3 = __uint_as_float((unsigned)(acc23 >> 32));
        float y = (a0 + a1) + (a2 + a3) + bias;
        omax = fmaxf(omax, y);
    }
    outs[ql * 64 + d] = omax;
    __syncthreads();

    // Transposed store: out[b][d][n], contiguous q within each row
    int d2 = tid >> 1, q2 = tid & 1;
    out[(b * 64 + d2) * N_ + q0 + q2] = outs[q2 * 64 + d2];
}

// ---------------------------------------------------------------------------
extern "C" void kernel_launch(void* const* d_in, const int* in_sizes, int n_in,
                              void* d_out, int out_size) {
    const float* coor  = (const float*)d_in[0];
    const float* fea   = (const float*)d_in[1];
    const float* W     = (const float*)d_in[2];
    const float* gamma = (const float*)d_in[3];
    const float* beta  = (const float*)d_in[4];
    const float* rmean = (const float*)d_in[5];
    const float* rvar  = (const float*)d_in[6];
    float* out = (float*)d_out;

    knn_kernel<<<dim3(N_ / 8, B_), 256>>>(coor, fea);
    agg_kernel<<<dim3(N_ / QPB, B_), 128>>>(coor, W, gamma, beta, rmean, rvar, out);
}

// round 3
// speedup vs baseline: 1.2388x; 1.1396x over previous
#include <cuda_runtime.h>

#define B_ 4
#define C_ 64
#define N_ 8192
#define K_ 32
#define R2_ 0.04f
#define BN_EPS_ 1e-5f
#define QPB 2   // queries per block in aggregation

typedef unsigned long long ull;

#define FMA2(acc, a, bb) asm("fma.rn.f32x2 %0, %1, %2, %0;" : "+l"(acc) : "l"(a), "l"(bb))

// Scratch (static __device__ arrays — no allocation)
__device__ float g_feaT[B_ * N_ * C_];   // (B, N, C) transposed features
__device__ int   g_gidx[B_ * N_ * K_];   // final (masked) neighbor indices

// ---------------------------------------------------------------------------
// KNN: one warp per query. Distributed top-32 heap: one (dist, idx) slot per
// lane. Candidates pruned at R^2 (ball-query mask means far neighbors are
// replaced by self anyway). Insert via redux-max + ballot + shfl.
// Prologue also performs the (B,C,N)->(B,N,C) feature transpose.
// NOTE: arithmetic here must stay bit-identical across rounds (selection
// order fixes the achieved rel_err).
// ---------------------------------------------------------------------------
__global__ __launch_bounds__(256) void knn_kernel(const float* __restrict__ coor,
                                                  const float* __restrict__ fea) {
    // ---- fused feature transpose (coalesced reads, strided writes) ----
    {
        int gid = (blockIdx.y * gridDim.x + blockIdx.x) * blockDim.x + threadIdx.x;
        int gstride = gridDim.x * gridDim.y * blockDim.x;
        for (int e = gid; e < B_ * C_ * N_; e += gstride) {
            int b = e / (C_ * N_);
            int r = e % (C_ * N_);
            int c = r / N_;
            int n = r % N_;
            g_feaT[(b * N_ + n) * C_ + c] = fea[e];
        }
    }

    __shared__ float4 tile[1024];
    const int b    = blockIdx.y;
    const int warp = threadIdx.x >> 5;
    const int lane = threadIdx.x & 31;
    const int q    = blockIdx.x * 8 + warp;

    const float* cb = coor + b * 3 * N_;
    const float qx  = cb[q];
    const float qy  = cb[N_ + q];
    const float qz  = cb[2 * N_ + q];
    const float qsq = fmaf(qx, qx, fmaf(qy, qy, qz * qz));

    float myd    = __int_as_float(0x7f800000);  // +inf
    int   myidx  = 0;
    float curmax = myd;
    int   maxlane = 0;

    for (int tbase = 0; tbase < N_; tbase += 1024) {
        __syncthreads();
#pragma unroll
        for (int i = 0; i < 4; i++) {
            int j = threadIdx.x + i * 256;
            int n = tbase + j;
            float x = cb[n], y = cb[N_ + n], z = cb[2 * N_ + n];
            tile[j] = make_float4(x, y, z, fmaf(x, x, fmaf(y, y, z * z)));
        }
        __syncthreads();
#pragma unroll 4
        for (int s = 0; s < 32; s++) {
            float4 c4 = tile[s * 32 + lane];
            float dot = fmaf(qx, c4.x, fmaf(qy, c4.y, qz * c4.z));
            float d   = fmaf(-2.f, dot, qsq + c4.w);
            d = fmaxf(d, 0.f);  // keep float-as-uint compare monotonic
            int cidx = tbase + s * 32 + lane;
            bool ok = (d <= R2_) && (d < curmax);
            unsigned mask = __ballot_sync(0xffffffffu, ok);
            while (mask) {
                int j2 = __ffs(mask) - 1;
                mask &= mask - 1;
                float dj = __shfl_sync(0xffffffffu, d, j2);
                int   cj = __shfl_sync(0xffffffffu, cidx, j2);
                if (dj < curmax) {  // warp-uniform
                    if (lane == maxlane) { myd = dj; myidx = cj; }
                    unsigned cm = __reduce_max_sync(0xffffffffu, __float_as_uint(myd));
                    curmax  = __uint_as_float(cm);
                    maxlane = __ffs(__ballot_sync(0xffffffffu,
                                        __float_as_uint(myd) == cm)) - 1;
                }
            }
        }
    }
    int finalIdx = (myd <= R2_) ? myidx : q;
    g_gidx[(b * N_ + q) * K_ + lane] = finalIdx;
}

// ---------------------------------------------------------------------------
// Aggregation, register-tiled: block = 256 threads, QPB=2 queries.
// Each thread owns a 4k x 4d tile of one query's (32 x 64) output, with the
// c-reduction (67+1 pad) packed pairwise into fma.rn.f32x2. Shared holds the
// BN-folded W (row-permuted for conflict-free LDS) and the gathered g tile.
// ---------------------------------------------------------------------------
__global__ __launch_bounds__(256, 3) void agg_kernel(
    const float* __restrict__ coor,
    const float* __restrict__ W,
    const float* __restrict__ gamma_, const float* __restrict__ beta_,
    const float* __restrict__ rmean, const float* __restrict__ rvar,
    float* __restrict__ out)
{
    __shared__ __align__(16) float Ws[64 * 68];        // row p(d), BN-scaled
    __shared__ __align__(16) float gs[QPB * 32 * 68];  // gathered [q][k][c]
    __shared__ __align__(16) float sred[QPB * 4 * 64]; // per-warp partial max
    __shared__ float sscale[64], sbias[64];
    __shared__ int   sIdx[QPB * 32];

    const int b   = blockIdx.y;
    const int q0  = blockIdx.x * QPB;
    const int tid = threadIdx.x;
    const int ql  = tid >> 7;          // local query 0..1
    const int kt  = (tid >> 4) & 7;    // k-tile 0..7  (k = kt*4 .. +3)
    const int dt  = tid & 15;          // d-tile 0..15 (d = dt*4 .. +3)

    // ---- phase A: BN constants + neighbor indices ----
    if (tid < 64) {
        float sc = gamma_[tid] * rsqrtf(rvar[tid] + BN_EPS_);
        sscale[tid] = sc;
        sbias[tid]  = beta_[tid] - rmean[tid] * sc;
    }
    if (tid >= 128 && tid < 128 + QPB * 32) {
        int e = tid - 128;
        sIdx[e] = g_gidx[(b * N_ + q0 + (e >> 5)) * K_ + (e & 31)];
    }
    __syncthreads();

    // ---- phase B: stage BN-folded W (row-permuted) + gathered g ----
    // permutation p(d) = (d&3)*16 + (d>>2): a d-tile's 4 rows land 16 rows
    // apart -> lane stride 272B = 16B bank-slot stride mod 128 (2-wavefront
    // minimum, no multi-way conflicts).
    for (int e = tid; e < 64 * 67; e += 256) {
        int dch = e / 67, c = e % 67;
        int p = (dch & 3) * 16 + (dch >> 2);
        Ws[p * 68 + c] = W[e] * sscale[dch];
    }
    if (tid < 64) Ws[tid * 68 + 67] = 0.f;

    const float* cb = coor + b * 3 * N_;
    for (int e = tid; e < QPB * 32 * 68; e += 256) {
        int q = e / (32 * 68);
        int r = e % (32 * 68);
        int k = r / 68;
        int c = r % 68;
        int id = sIdx[q * 32 + k];
        float v;
        if (c < 64) {
            v = g_feaT[(b * N_ + id) * 64 + c];
        } else if (c < 67) {
            int ax = c - 64;
            v = (cb[ax * N_ + id] - cb[ax * N_ + q0 + q]) * 5.0f;  // /RADIUS
        } else {
            v = 0.f;
        }
        gs[e] = v;
    }
    __syncthreads();

    // ---- main loop: 4k x 4d outer product, c packed as f32x2 ----
    const ulonglong2* __restrict__ grow =
        reinterpret_cast<const ulonglong2*>(&gs[(ql * 32 + kt * 4) * 68]);
    const ulonglong2* __restrict__ wrow =
        reinterpret_cast<const ulonglong2*>(&Ws[dt * 68]);

    ull acc[4][4];
#pragma unroll
    for (int kk = 0; kk < 4; kk++)
#pragma unroll
        for (int dd = 0; dd < 4; dd++) acc[kk][dd] = 0ull;

    for (int ch = 0; ch < 17; ch++) {
        ulonglong2 gv[4], wv[4];
#pragma unroll
        for (int kk = 0; kk < 4; kk++) gv[kk] = grow[kk * 17 + ch];
#pragma unroll
        for (int dd = 0; dd < 4; dd++) wv[dd] = wrow[dd * 272 + ch];
#pragma unroll
        for (int kk = 0; kk < 4; kk++)
#pragma unroll
            for (int dd = 0; dd < 4; dd++) {
                FMA2(acc[kk][dd], gv[kk].x, wv[dd].x);
                FMA2(acc[kk][dd], gv[kk].y, wv[dd].y);
            }
    }

    // ---- epilogue: bias + ReLU + max over k ----
    float vmax[4];
#pragma unroll
    for (int dd = 0; dd < 4; dd++) {
        float bia = sbias[dt * 4 + dd];
        float m = 0.f;  // ReLU identity
#pragma unroll
        for (int kk = 0; kk < 4; kk++) {
            float2 p = *reinterpret_cast<float2*>(&acc[kk][dd]);
            m = fmaxf(m, (p.x + p.y) + bia);
        }
        vmax[dd] = m;
    }
#pragma unroll
    for (int dd = 0; dd < 4; dd++)
        vmax[dd] = fmaxf(vmax[dd], __shfl_xor_sync(0xffffffffu, vmax[dd], 16));

    const int lane = tid & 31;
    const int wq   = (tid >> 5) & 3;   // warp within query
    if (lane < 16) {
        float4 v4 = make_float4(vmax[0], vmax[1], vmax[2], vmax[3]);
        *reinterpret_cast<float4*>(&sred[((ql * 4 + wq) * 16 + dt) * 4]) = v4;
    }
    __syncthreads();

    if (tid < QPB * 64) {
        int q = tid >> 6, d = tid & 63;
        float m =          sred[(q * 4 + 0) * 64 + d];
        m = fmaxf(m,       sred[(q * 4 + 1) * 64 + d]);
        m = fmaxf(m,       sred[(q * 4 + 2) * 64 + d]);
        m = fmaxf(m,       sred[(q * 4 + 3) * 64 + d]);
        out[(b * 64 + d) * N_ + q0 + q] = m;
    }
}

// ---------------------------------------------------------------------------
extern "C" void kernel_launch(void* const* d_in, const int* in_sizes, int n_in,
                              void* d_out, int out_size) {
    const float* coor  = (const float*)d_in[0];
    const float* fea   = (const float*)d_in[1];
    const float* W     = (const float*)d_in[2];
    const float* gamma = (const float*)d_in[3];
    const float* beta  = (const float*)d_in[4];
    const float* rmean = (const float*)d_in[5];
    const float* rvar  = (const float*)d_in[6];
    float* out = (float*)d_out;

    knn_kernel<<<dim3(N_ / 8, B_), 256>>>(coor, fea);
    agg_kernel<<<dim3(N_ / QPB, B_), 256>>>(coor, W, gamma, beta, rmean, rvar, out);
}

// round 4
// speedup vs baseline: 1.4143x; 1.1417x over previous
#include <cuda_runtime.h>

#define B_ 4
#define C_ 64
#define N_ 8192
#define K_ 32
#define R2_ 0.04f
#define BN_EPS_ 1e-5f
#define QPB 2   // queries per block in aggregation

typedef unsigned long long ull;

#define FMA2ACC(acc, a, bb) asm("fma.rn.f32x2 %0, %1, %2, %0;" : "+l"(acc) : "l"(a), "l"(bb))

__device__ __forceinline__ ull fma2(ull a, ull b, ull c) {
    ull r; asm("fma.rn.f32x2 %0, %1, %2, %3;" : "=l"(r) : "l"(a), "l"(b), "l"(c)); return r;
}
__device__ __forceinline__ ull mul2(ull a, ull b) {
    ull r; asm("mul.rn.f32x2 %0, %1, %2;" : "=l"(r) : "l"(a), "l"(b)); return r;
}
__device__ __forceinline__ ull add2(ull a, ull b) {
    ull r; asm("add.rn.f32x2 %0, %1, %2;" : "=l"(r) : "l"(a), "l"(b)); return r;
}
__device__ __forceinline__ ull pack2(float lo, float hi) {
    ull r; asm("mov.b64 %0, {%1, %2};" : "=l"(r) : "f"(lo), "f"(hi)); return r;
}
__device__ __forceinline__ void unpack2(ull v, float& lo, float& hi) {
    asm("mov.b64 {%0, %1}, %2;" : "=f"(lo), "=f"(hi) : "l"(v));
}

// Scratch (static __device__ arrays — no allocation)
__device__ float  g_feaT[B_ * N_ * C_];   // (B, N, C) transposed features
__device__ int    g_gidx[B_ * N_ * K_];   // final (masked) neighbor indices
__device__ float4 g_W3[17 * 4 * 16];      // BN-folded W, [ch][dd][dt] lane layout
__device__ float  g_bias[64];             // BN-folded bias

// ---------------------------------------------------------------------------
// Prep: (a) tiled (B,C,N)->(B,N,C) transpose, coalesced on both sides;
//       (b) one extra block folds BN into W with the [ch][dd][dt] layout the
//           agg main loop consumes (lane dt contiguous -> 2-line LDG.128).
// ---------------------------------------------------------------------------
__global__ __launch_bounds__(256) void prep_kernel(
    const float* __restrict__ fea, const float* __restrict__ W,
    const float* __restrict__ gamma_, const float* __restrict__ beta_,
    const float* __restrict__ rmean, const float* __restrict__ rvar)
{
    const int bid = blockIdx.x;
    const int tid = threadIdx.x;
    if (bid == B_ * 2 * 256) {
        // ---- W fold + relayout + bias ----
        if (tid < 64) {
            float sc = gamma_[tid] * rsqrtf(rvar[tid] + BN_EPS_);
            g_bias[tid] = beta_[tid] - rmean[tid] * sc;
        }
        for (int e = tid; e < 17 * 4 * 16; e += 256) {
            int ch = e >> 6;           // 0..16
            int dd = (e >> 4) & 3;
            int dt = e & 15;
            int d  = dt * 4 + dd;
            float sc = gamma_[d] * rsqrtf(rvar[d] + BN_EPS_);
            int c0 = ch * 4;
            float4 v;
            v.x = (c0 + 0 < 67) ? W[d * 67 + c0 + 0] * sc : 0.f;
            v.y = (c0 + 1 < 67) ? W[d * 67 + c0 + 1] * sc : 0.f;
            v.z = (c0 + 2 < 67) ? W[d * 67 + c0 + 2] * sc : 0.f;
            v.w = (c0 + 3 < 67) ? W[d * 67 + c0 + 3] * sc : 0.f;
            g_W3[e] = v;
        }
        return;
    }
    // ---- transpose: bid = (b*2 + cblk)*256 + nblk ----
    __shared__ float t[32][33];
    const int nblk = bid & 255;
    const int cblk = (bid >> 8) & 1;
    const int b    = bid >> 9;
    const int lane = tid & 31, w = tid >> 5;
    const int c0 = cblk * 32, n0 = nblk * 32;
    const float* src = fea + (b * 64 + c0) * N_ + n0;
#pragma unroll
    for (int i = w; i < 32; i += 8) t[i][lane] = src[i * N_ + lane];
    __syncthreads();
    float* dst = g_feaT + (b * N_ + n0) * 64 + c0;
#pragma unroll
    for (int i = w; i < 32; i += 8) dst[i * 64 + lane] = t[lane][i];
}

// ---------------------------------------------------------------------------
// KNN: one warp per query, distributed top-32 heap (one slot per lane).
// Distances computed two-at-a-time with f32x2 ops (bit-identical to the
// scalar fmaf chain). Inserts are merged across the two ballot masks in
// strictly increasing candidate index, so the selected set — including all
// boundary-tie behavior — is exactly the same as the scalar version.
// ---------------------------------------------------------------------------
__global__ __launch_bounds__(256) void knn_kernel(const float* __restrict__ coor) {
    __shared__ ull sx[512], sy[512], sz[512], ssq[512];  // candidate pairs (SoA)

    const int b    = blockIdx.y;
    const int warp = threadIdx.x >> 5;
    const int lane = threadIdx.x & 31;
    const int q    = blockIdx.x * 8 + warp;

    const float* cb = coor + b * 3 * N_;
    const float qx  = cb[q];
    const float qy  = cb[N_ + q];
    const float qz  = cb[2 * N_ + q];
    const float qsq = fmaf(qx, qx, fmaf(qy, qy, qz * qz));

    const ull qx2  = pack2(qx, qx);
    const ull qy2  = pack2(qy, qy);
    const ull qz2  = pack2(qz, qz);
    const ull qsq2 = pack2(qsq, qsq);
    const ull m2   = pack2(-2.f, -2.f);

    float myd    = __int_as_float(0x7f800000);  // +inf
    int   myidx  = 0;
    float curmax = myd;
    int   maxlane = 0;

    for (int tbase = 0; tbase < N_; tbase += 1024) {
        __syncthreads();
        // stage 512 candidate pairs (SoA, packed f32x2)
        for (int pi = threadIdx.x; pi < 512; pi += 256) {
            int n = tbase + 2 * pi;
            float2 x2 = *reinterpret_cast<const float2*>(cb + n);
            float2 y2 = *reinterpret_cast<const float2*>(cb + N_ + n);
            float2 z2 = *reinterpret_cast<const float2*>(cb + 2 * N_ + n);
            ull xs = *reinterpret_cast<ull*>(&x2);
            ull ys = *reinterpret_cast<ull*>(&y2);
            ull zs = *reinterpret_cast<ull*>(&z2);
            sx[pi] = xs; sy[pi] = ys; sz[pi] = zs;
            ssq[pi] = fma2(xs, xs, fma2(ys, ys, mul2(zs, zs)));
        }
        __syncthreads();
#pragma unroll 2
        for (int s = 0; s < 16; s++) {
            int pi = s * 32 + lane;
            ull x2 = sx[pi], y2 = sy[pi], z2 = sz[pi], sq2 = ssq[pi];
            ull dot2 = fma2(qx2, x2, fma2(qy2, y2, mul2(qz2, z2)));
            ull d2   = fma2(m2, dot2, add2(qsq2, sq2));
            float d0, d1; unpack2(d2, d0, d1);
            d0 = fmaxf(d0, 0.f);   // keep float-as-uint compare monotonic
            d1 = fmaxf(d1, 0.f);
            int c0i = tbase + 2 * pi;
            bool ok0 = (d0 <= R2_) && (d0 < curmax);
            bool ok1 = (d1 <= R2_) && (d1 < curmax);
            unsigned m0 = __ballot_sync(0xffffffffu, ok0);
            unsigned m1 = __ballot_sync(0xffffffffu, ok1);
            while (m0 | m1) {
                int j0 = __ffs(m0) - 1;
                int j1 = __ffs(m1) - 1;
                unsigned u0 = m0 ? (unsigned)(2 * j0)     : 0xffffffffu;
                unsigned u1 = m1 ? (unsigned)(2 * j1 + 1) : 0xffffffffu;
                bool use0 = u0 < u1;             // warp-uniform
                int j = use0 ? j0 : j1;
                float dsel = use0 ? d0 : d1;
                int   csel = use0 ? c0i : (c0i + 1);
                float dj = __shfl_sync(0xffffffffu, dsel, j);
                int   cj = __shfl_sync(0xffffffffu, csel, j);
                if (use0) m0 &= m0 - 1; else m1 &= m1 - 1;
                if (dj < curmax) {               // warp-uniform
                    if (lane == maxlane) { myd = dj; myidx = cj; }
                    unsigned cm = __reduce_max_sync(0xffffffffu, __float_as_uint(myd));
                    curmax  = __uint_as_float(cm);
                    maxlane = __ffs(__ballot_sync(0xffffffffu,
                                        __float_as_uint(myd) == cm)) - 1;
                }
            }
        }
    }
    int finalIdx = (myd <= R2_) ? myidx : q;
    g_gidx[(b * N_ + q) * K_ + lane] = finalIdx;
}

// ---------------------------------------------------------------------------
// Aggregation, register-tiled 4k x 4d per thread, c packed into f32x2.
// W comes pre-folded from g_W3 (L1-resident, lane-matched layout) — no W
// staging. g rows gathered warp-per-row (coalesced LDG.64/STS.64, no div/mod).
// ---------------------------------------------------------------------------
__global__ __launch_bounds__(256, 3) void agg_kernel(
    const float* __restrict__ coor,
    float* __restrict__ out)
{
    __shared__ __align__(16) float gs[QPB * 32 * 68];  // gathered [q][k][c]
    __shared__ __align__(16) float sred[QPB * 4 * 64]; // per-warp partial max
    __shared__ int sIdx[QPB * 32];

    const int b    = blockIdx.y;
    const int q0   = blockIdx.x * QPB;
    const int tid  = threadIdx.x;
    const int ql   = tid >> 7;          // local query 0..1
    const int kt   = (tid >> 4) & 7;    // k-tile 0..7
    const int dt   = tid & 15;          // d-tile 0..15
    const int lane = tid & 31;
    const int wid  = tid >> 5;

    // ---- neighbor indices ----
    if (tid < QPB * 32) {
        sIdx[tid] = g_gidx[(b * N_ + q0 + (tid >> 5)) * K_ + (tid & 31)];
    }
    __syncthreads();

    // ---- gather g rows: one warp per row, 8 rows per warp ----
    const float* cb = coor + b * 3 * N_;
#pragma unroll
    for (int i = 0; i < 8; i++) {
        int row = wid + i * 8;          // (q,k) = (row>>5, row&31)
        int id = sIdx[row];
        ull v = reinterpret_cast<const ull*>(g_feaT + (b * N_ + id) * 64)[lane];
        reinterpret_cast<ull*>(gs + row * 68)[lane] = v;
        if (lane < 3) {
            gs[row * 68 + 64 + lane] =
                (cb[lane * N_ + id] - cb[lane * N_ + q0 + (row >> 5)]) * 5.0f; // /RADIUS
        } else if (lane == 3) {
            gs[row * 68 + 67] = 0.f;
        }
    }
    __syncthreads();

    // ---- main loop: 4k x 4d outer product, c packed as f32x2 ----
    const ulonglong2* __restrict__ grow =
        reinterpret_cast<const ulonglong2*>(&gs[(ql * 32 + kt * 4) * 68]);
    const ulonglong2* __restrict__ w3 =
        reinterpret_cast<const ulonglong2*>(g_W3) + dt;

    ull acc[4][4];
#pragma unroll
    for (int kk = 0; kk < 4; kk++)
#pragma unroll
        for (int dd = 0; dd < 4; dd++) acc[kk][dd] = 0ull;

    for (int ch = 0; ch < 17; ch++) {
        ulonglong2 gv[4], wv[4];
#pragma unroll
        for (int kk = 0; kk < 4; kk++) gv[kk] = grow[kk * 17 + ch];
#pragma unroll
        for (int dd = 0; dd < 4; dd++) wv[dd] = __ldg(&w3[(ch * 4 + dd) * 16]);
#pragma unroll
        for (int kk = 0; kk < 4; kk++)
#pragma unroll
            for (int dd = 0; dd < 4; dd++) {
                FMA2ACC(acc[kk][dd], gv[kk].x, wv[dd].x);
                FMA2ACC(acc[kk][dd], gv[kk].y, wv[dd].y);
            }
    }

    // ---- epilogue: bias + ReLU + max over k ----
    float vmax[4];
#pragma unroll
    for (int dd = 0; dd < 4; dd++) {
        float bia = g_bias[dt * 4 + dd];
        float m = 0.f;  // ReLU identity
#pragma unroll
        for (int kk = 0; kk < 4; kk++) {
            float2 p = *reinterpret_cast<float2*>(&acc[kk][dd]);
            m = fmaxf(m, (p.x + p.y) + bia);
        }
        vmax[dd] = m;
    }
#pragma unroll
    for (int dd = 0; dd < 4; dd++)
        vmax[dd] = fmaxf(vmax[dd], __shfl_xor_sync(0xffffffffu, vmax[dd], 16));

    const int wq = (tid >> 5) & 3;   // warp within query
    if (lane < 16) {
        float4 v4 = make_float4(vmax[0], vmax[1], vmax[2], vmax[3]);
        *reinterpret_cast<float4*>(&sred[((ql * 4 + wq) * 16 + dt) * 4]) = v4;
    }
    __syncthreads();

    if (tid < QPB * 64) {
        int q = tid >> 6, d = tid & 63;
        float m =    sred[(q * 4 + 0) * 64 + d];
        m = fmaxf(m, sred[(q * 4 + 1) * 64 + d]);
        m = fmaxf(m, sred[(q * 4 + 2) * 64 + d]);
        m = fmaxf(m, sred[(q * 4 + 3) * 64 + d]);
        out[(b * 64 + d) * N_ + q0 + q] = m;
    }
}

// ---------------------------------------------------------------------------
extern "C" void kernel_launch(void* const* d_in, const int* in_sizes, int n_in,
                              void* d_out, int out_size) {
    const float* coor  = (const float*)d_in[0];
    const float* fea   = (const float*)d_in[1];
    const float* W     = (const float*)d_in[2];
    const float* gamma = (const float*)d_in[3];
    const float* beta  = (const float*)d_in[4];
    const float* rmean = (const float*)d_in[5];
    const float* rvar  = (const float*)d_in[6];
    float* out = (float*)d_out;

    prep_kernel<<<B_ * 2 * 256 + 1, 256>>>(fea, W, gamma, beta, rmean, rvar);
    knn_kernel<<<dim3(N_ / 8, B_), 256>>>(coor);
    agg_kernel<<<dim3(N_ / QPB, B_), 256>>>(coor, out);
}

// round 5
// speedup vs baseline: 2.6301x; 1.8596x over previous
#include <cuda_runtime.h>

#define B_ 4
#define C_ 64
#define N_ 8192
#define K_ 32
#define R2_ 0.04f
#define BN_EPS_ 1e-5f

typedef unsigned long long ull;

#define FMA2ACC(acc, a, bb) asm("fma.rn.f32x2 %0, %1, %2, %0;" : "+l"(acc) : "l"(a), "l"(bb))

__device__ __forceinline__ ull fma2(ull a, ull b, ull c) {
    ull r; asm("fma.rn.f32x2 %0, %1, %2, %3;" : "=l"(r) : "l"(a), "l"(b), "l"(c)); return r;
}
__device__ __forceinline__ ull mul2(ull a, ull b) {
    ull r; asm("mul.rn.f32x2 %0, %1, %2;" : "=l"(r) : "l"(a), "l"(b)); return r;
}
__device__ __forceinline__ ull add2(ull a, ull b) {
    ull r; asm("add.rn.f32x2 %0, %1, %2;" : "=l"(r) : "l"(a), "l"(b)); return r;
}
__device__ __forceinline__ ull pack2(float lo, float hi) {
    ull r; asm("mov.b64 %0, {%1, %2};" : "=l"(r) : "f"(lo), "f"(hi)); return r;
}
__device__ __forceinline__ void unpack2(ull v, float& lo, float& hi) {
    asm("mov.b64 {%0, %1}, %2;" : "=f"(lo), "=f"(hi) : "l"(v));
}

// Scratch (static __device__ arrays — no allocation)
__device__ float g_feaT[B_ * N_ * C_];   // (B, N, C) transposed features
__device__ float g_F[B_ * N_ * C_];      // F[b][n][d] = fea row . W_fea[d] * scale
__device__ int   g_gidx[B_ * N_ * K_];   // final (masked) neighbor indices
__device__ ull   g_WsT2[32 * 64];        // packed (w[2c],w[2c+1]) per d, BN-scaled
__device__ float g_Wc[3 * 64];           // coord weights * scale
__device__ float g_bias[64];             // BN-folded bias

// ---------------------------------------------------------------------------
// Prep: (a) tiled (B,C,N)->(B,N,C) transpose, coalesced both sides;
//       (b) one extra block folds BN scale into W: paired-c layout for the
//           F GEMM, coord weights, bias.
// ---------------------------------------------------------------------------
__global__ __launch_bounds__(256) void prep_kernel(
    const float* __restrict__ fea, const float* __restrict__ W,
    const float* __restrict__ gamma_, const float* __restrict__ beta_,
    const float* __restrict__ rmean, const float* __restrict__ rvar)
{
    const int bid = blockIdx.x;
    const int tid = threadIdx.x;
    if (bid == B_ * 2 * 256) {
        if (tid < 64) {
            float sc = gamma_[tid] * rsqrtf(rvar[tid] + BN_EPS_);
            g_bias[tid] = beta_[tid] - rmean[tid] * sc;
            g_Wc[tid]       = W[tid * 67 + 64] * sc;
            g_Wc[64 + tid]  = W[tid * 67 + 65] * sc;
            g_Wc[128 + tid] = W[tid * 67 + 66] * sc;
        }
        for (int e = tid; e < 32 * 64; e += 256) {
            int c2 = e >> 6, d = e & 63;
            float sc = gamma_[d] * rsqrtf(rvar[d] + BN_EPS_);
            g_WsT2[e] = pack2(W[d * 67 + 2 * c2] * sc, W[d * 67 + 2 * c2 + 1] * sc);
        }
        return;
    }
    // ---- transpose: bid = (b*2 + cblk)*256 + nblk ----
    __shared__ float t[32][33];
    const int nblk = bid & 255;
    const int cblk = (bid >> 8) & 1;
    const int b    = bid >> 9;
    const int lane = tid & 31, w = tid >> 5;
    const int c0 = cblk * 32, n0 = nblk * 32;
    const float* src = fea + (b * 64 + c0) * N_ + n0;
#pragma unroll
    for (int i = w; i < 32; i += 8) t[i][lane] = src[i * N_ + lane];
    __syncthreads();
    float* dst = g_feaT + (b * N_ + n0) * 64 + c0;
#pragma unroll
    for (int i = w; i < 32; i += 8) dst[i * 64 + lane] = t[lane][i];
}

// ---------------------------------------------------------------------------
// F GEMM: F[b][n][d] = feaT[b][n][:] . WsT2[:][d]  (BN scale pre-folded).
// Block = 256 threads = 4 n x 64 d. Both operands staged in shared; the
// c-reduction runs pairwise via fma.rn.f32x2.
// ---------------------------------------------------------------------------
__global__ __launch_bounds__(256) void fgemm_kernel() {
    __shared__ ull   s_wt[32 * 64];               // 16 KB
    __shared__ __align__(16) float sfea[4 * 64];
    const int b  = blockIdx.y, n0 = blockIdx.x * 4;
    const int tid = threadIdx.x;
    const int nl = tid >> 6, d = tid & 63;

    for (int e = tid; e < 32 * 64; e += 256) s_wt[e] = g_WsT2[e];
    sfea[tid] = g_feaT[(b * N_ + n0 + nl) * 64 + d];   // e==(nl,d) reuse: coalesced
    __syncthreads();

    const ull* frow = reinterpret_cast<const ull*>(sfea + nl * 64);
    ull acc = 0ull;
#pragma unroll
    for (int c2 = 0; c2 < 32; c2++)
        FMA2ACC(acc, frow[c2], s_wt[c2 * 64 + d]);
    float lo, hi; unpack2(acc, lo, hi);
    g_F[(b * N_ + n0 + nl) * 64 + d] = lo + hi;
}

// ---------------------------------------------------------------------------
// KNN: one warp per query, distributed top-32 heap (one slot per lane).
// BIT-IDENTICAL to R4 (selection order fixes the achieved rel_err).
// ---------------------------------------------------------------------------
__global__ __launch_bounds__(256) void knn_kernel(const float* __restrict__ coor) {
    __shared__ ull sx[512], sy[512], sz[512], ssq[512];  // candidate pairs (SoA)

    const int b    = blockIdx.y;
    const int warp = threadIdx.x >> 5;
    const int lane = threadIdx.x & 31;
    const int q    = blockIdx.x * 8 + warp;

    const float* cb = coor + b * 3 * N_;
    const float qx  = cb[q];
    const float qy  = cb[N_ + q];
    const float qz  = cb[2 * N_ + q];
    const float qsq = fmaf(qx, qx, fmaf(qy, qy, qz * qz));

    const ull qx2  = pack2(qx, qx);
    const ull qy2  = pack2(qy, qy);
    const ull qz2  = pack2(qz, qz);
    const ull qsq2 = pack2(qsq, qsq);
    const ull m2   = pack2(-2.f, -2.f);

    float myd    = __int_as_float(0x7f800000);  // +inf
    int   myidx  = 0;
    float curmax = myd;
    int   maxlane = 0;

    for (int tbase = 0; tbase < N_; tbase += 1024) {
        __syncthreads();
        for (int pi = threadIdx.x; pi < 512; pi += 256) {
            int n = tbase + 2 * pi;
            float2 x2 = *reinterpret_cast<const float2*>(cb + n);
            float2 y2 = *reinterpret_cast<const float2*>(cb + N_ + n);
            float2 z2 = *reinterpret_cast<const float2*>(cb + 2 * N_ + n);
            ull xs = *reinterpret_cast<ull*>(&x2);
            ull ys = *reinterpret_cast<ull*>(&y2);
            ull zs = *reinterpret_cast<ull*>(&z2);
            sx[pi] = xs; sy[pi] = ys; sz[pi] = zs;
            ssq[pi] = fma2(xs, xs, fma2(ys, ys, mul2(zs, zs)));
        }
        __syncthreads();
#pragma unroll 2
        for (int s = 0; s < 16; s++) {
            int pi = s * 32 + lane;
            ull x2 = sx[pi], y2 = sy[pi], z2 = sz[pi], sq2 = ssq[pi];
            ull dot2 = fma2(qx2, x2, fma2(qy2, y2, mul2(qz2, z2)));
            ull d2   = fma2(m2, dot2, add2(qsq2, sq2));
            float d0, d1; unpack2(d2, d0, d1);
            d0 = fmaxf(d0, 0.f);
            d1 = fmaxf(d1, 0.f);
            int c0i = tbase + 2 * pi;
            bool ok0 = (d0 <= R2_) && (d0 < curmax);
            bool ok1 = (d1 <= R2_) && (d1 < curmax);
            unsigned m0 = __ballot_sync(0xffffffffu, ok0);
            unsigned m1 = __ballot_sync(0xffffffffu, ok1);
            while (m0 | m1) {
                int j0 = __ffs(m0) - 1;
                int j1 = __ffs(m1) - 1;
                unsigned u0 = m0 ? (unsigned)(2 * j0)     : 0xffffffffu;
                unsigned u1 = m1 ? (unsigned)(2 * j1 + 1) : 0xffffffffu;
                bool use0 = u0 < u1;             // warp-uniform
                int j = use0 ? j0 : j1;
                float dsel = use0 ? d0 : d1;
                int   csel = use0 ? c0i : (c0i + 1);
                float dj = __shfl_sync(0xffffffffu, dsel, j);
                int   cj = __shfl_sync(0xffffffffu, csel, j);
                if (use0) m0 &= m0 - 1; else m1 &= m1 - 1;
                if (dj < curmax) {               // warp-uniform
                    if (lane == maxlane) { myd = dj; myidx = cj; }
                    unsigned cm = __reduce_max_sync(0xffffffffu, __float_as_uint(myd));
                    curmax  = __uint_as_float(cm);
                    maxlane = __ffs(__ballot_sync(0xffffffffu,
                                        __float_as_uint(myd) == cm)) - 1;
                }
            }
        }
    }
    int finalIdx = (myd <= R2_) ? myidx : q;
    g_gidx[(b * N_ + q) * K_ + lane] = finalIdx;
}

// ---------------------------------------------------------------------------
// Aggregation: y[q,k,d] = F[id_k][d] + gcoor.Wc[d] + bias[d]; ReLU+max over k.
// Block = 256 threads = 4 queries x 64 d. F rows are 256 B, warp-coalesced,
// L2-resident (8 MB). Only 3 FMAs per element remain.
// ---------------------------------------------------------------------------
__global__ __launch_bounds__(256) void agg_kernel(const float* __restrict__ coor,
                                                  float* __restrict__ out) {
    __shared__ int   sIdx[4 * 32];
    __shared__ float scx[4 * 32], scy[4 * 32], scz[4 * 32];
    __shared__ float sout[4 * 64];

    const int b   = blockIdx.y;
    const int q0  = blockIdx.x * 4;
    const int tid = threadIdx.x;
    const int q   = tid >> 6, d = tid & 63;
    const float* cb = coor + b * 3 * N_;

    if (tid < 128) {
        int qq = tid >> 5, k = tid & 31;
        int id = g_gidx[(b * N_ + q0 + qq) * K_ + k];
        sIdx[tid] = id;
        scx[tid] = (cb[id] - cb[q0 + qq]) * 5.0f;                 // /RADIUS
        scy[tid] = (cb[N_ + id] - cb[N_ + q0 + qq]) * 5.0f;
        scz[tid] = (cb[2 * N_ + id] - cb[2 * N_ + q0 + qq]) * 5.0f;
    }
    __syncthreads();

    const float wx = g_Wc[d], wy = g_Wc[64 + d], wz = g_Wc[128 + d];
    const float bia = g_bias[d];
    const float* Fb = g_F + (size_t)(b * N_) * 64;

    float m = 0.f;  // ReLU identity
#pragma unroll 4
    for (int k = 0; k < 32; k++) {
        int id = sIdx[q * 32 + k];
        float f = __ldg(Fb + id * 64 + d);
        float y = fmaf(scx[q * 32 + k], wx, f);
        y = fmaf(scy[q * 32 + k], wy, y);
        y = fmaf(scz[q * 32 + k], wz, y);
        m = fmaxf(m, y + bia);
    }
    sout[q * 64 + d] = m;
    __syncthreads();

    // transposed store: 4 consecutive n's per d row (16B chunks)
    int d2 = tid >> 2, q2 = tid & 3;
    out[(b * 64 + d2) * N_ + q0 + q2] = sout[q2 * 64 + d2];
}

// ---------------------------------------------------------------------------
extern "C" void kernel_launch(void* const* d_in, const int* in_sizes, int n_in,
                              void* d_out, int out_size) {
    const float* coor  = (const float*)d_in[0];
    const float* fea   = (const float*)d_in[1];
    const float* W     = (const float*)d_in[2];
    const float* gamma = (const float*)d_in[3];
    const float* beta  = (const float*)d_in[4];
    const float* rmean = (const float*)d_in[5];
    const float* rvar  = (const float*)d_in[6];
    float* out = (float*)d_out;

    prep_kernel<<<B_ * 2 * 256 + 1, 256>>>(fea, W, gamma, beta, rmean, rvar);
    fgemm_kernel<<<dim3(N_ / 4, B_), 256>>>();
    knn_kernel<<<dim3(N_ / 8, B_), 256>>>(coor);
    agg_kernel<<<dim3(N_ / 4, B_), 256>>>(coor, out);
}

// round 7
// speedup vs baseline: 3.0963x; 1.1773x over previous
#include <cuda_runtime.h>

#define B_ 4
#define C_ 64
#define N_ 8192
#define K_ 32
#define R2_ 0.04f
#define BN_EPS_ 1e-5f
#define NC 5
#define NCELL (NC * NC * NC)

typedef unsigned long long ull;

#define FMA2ACC(acc, a, bb) asm("fma.rn.f32x2 %0, %1, %2, %0;" : "+l"(acc) : "l"(a), "l"(bb))

__device__ __forceinline__ ull pack2(float lo, float hi) {
    ull r; asm("mov.b64 %0, {%1, %2};" : "=l"(r) : "f"(lo), "f"(hi)); return r;
}
__device__ __forceinline__ void unpack2(ull v, float& lo, float& hi) {
    asm("mov.b64 {%0, %1}, %2;" : "=f"(lo), "=f"(hi) : "l"(v));
}
__device__ __forceinline__ int cell_clamp(float v) {
    int c = (int)(v * 5.0f);
    return min(NC - 1, max(0, c));
}

// Scratch (static __device__ arrays — no allocation)
__device__ float  g_feaT[B_ * N_ * C_];   // (B, N, C) transposed features
__device__ float  g_F[B_ * N_ * C_];      // F[b][n][d] = fea row . W_fea[d] * scale
__device__ int    g_gidx[B_ * N_ * K_];   // final (masked) neighbor indices
__device__ ull    g_WsT2[32 * 64];        // packed (w[2c],w[2c+1]) per d, BN-scaled
__device__ float  g_Wc[3 * 64];           // coord weights * scale
__device__ float  g_bias[64];             // BN-folded bias
// grid structures
__device__ int    g_cnt[B_ * NCELL];
__device__ int    g_cellStart[B_ * (NCELL + 1)];
__device__ int    g_cellCur[B_ * NCELL];
__device__ float4 g_pts[B_ * N_];         // cell-sorted (x,y,z,sq)
__device__ int    g_pid[B_ * N_];         // original point index

// ---------------------------------------------------------------------------
// Prep: (a) tiled (B,C,N)->(B,N,C) transpose; (b) extra block folds BN into W
// (paired-c layout for F GEMM, coord weights, bias) AND zeroes grid counters
// (must re-zero every call: graph replays).
// ---------------------------------------------------------------------------
__global__ __launch_bounds__(256) void prep_kernel(
    const float* __restrict__ fea, const float* __restrict__ W,
    const float* __restrict__ gamma_, const float* __restrict__ beta_,
    const float* __restrict__ rmean, const float* __restrict__ rvar)
{
    const int bid = blockIdx.x;
    const int tid = threadIdx.x;
    if (bid == B_ * 2 * 256) {
        if (tid < 64) {
            float sc = gamma_[tid] * rsqrtf(rvar[tid] + BN_EPS_);
            g_bias[tid] = beta_[tid] - rmean[tid] * sc;
            g_Wc[tid]       = W[tid * 67 + 64] * sc;
            g_Wc[64 + tid]  = W[tid * 67 + 65] * sc;
            g_Wc[128 + tid] = W[tid * 67 + 66] * sc;
        }
        for (int e = tid; e < 32 * 64; e += 256) {
            int c2 = e >> 6, d = e & 63;
            float sc = gamma_[d] * rsqrtf(rvar[d] + BN_EPS_);
            g_WsT2[e] = pack2(W[d * 67 + 2 * c2] * sc, W[d * 67 + 2 * c2 + 1] * sc);
        }
        for (int e = tid; e < B_ * NCELL; e += 256) g_cnt[e] = 0;
        return;
    }
    __shared__ float t[32][33];
    const int nblk = bid & 255;
    const int cblk = (bid >> 8) & 1;
    const int b    = bid >> 9;
    const int lane = tid & 31, w = tid >> 5;
    const int c0 = cblk * 32, n0 = nblk * 32;
    const float* src = fea + (b * 64 + c0) * N_ + n0;
#pragma unroll
    for (int i = w; i < 32; i += 8) t[i][lane] = src[i * N_ + lane];
    __syncthreads();
    float* dst = g_feaT + (b * N_ + n0) * 64 + c0;
#pragma unroll
    for (int i = w; i < 32; i += 8) dst[i * 64 + lane] = t[lane][i];
}

// ---------------------------------------------------------------------------
// Grid build: count -> scan -> scatter (cell-sorted SoA with precomputed sq)
// ---------------------------------------------------------------------------
__global__ __launch_bounds__(256) void grid_count(const float* __restrict__ coor) {
    int id = blockIdx.x * 256 + threadIdx.x;
    if (id >= B_ * N_) return;
    int b = id / N_, n = id % N_;
    const float* cb = coor + b * 3 * N_;
    int cx = cell_clamp(cb[n]);
    int cy = cell_clamp(cb[N_ + n]);
    int cz = cell_clamp(cb[2 * N_ + n]);
    atomicAdd(&g_cnt[b * NCELL + (cz * NC + cy) * NC + cx], 1);
}

__global__ void grid_scan() {
    int wb = threadIdx.x >> 5;
    int lane = threadIdx.x & 31;
    if (wb >= B_) return;
    if (lane == 0) g_cellStart[wb * (NCELL + 1)] = 0;
    int carry = 0;
    for (int c0 = 0; c0 < NCELL; c0 += 32) {
        int i = c0 + lane;
        int orig = (i < NCELL) ? g_cnt[wb * NCELL + i] : 0;
        int v = orig;
#pragma unroll
        for (int o = 1; o < 32; o <<= 1) {
            int tv = __shfl_up_sync(0xffffffffu, v, o);
            if (lane >= o) v += tv;
        }
        if (i < NCELL) {
            g_cellStart[wb * (NCELL + 1) + i + 1] = carry + v;
            g_cellCur[wb * NCELL + i] = carry + v - orig;
        }
        carry += __shfl_sync(0xffffffffu, v, 31);
    }
}

__global__ __launch_bounds__(256) void grid_scatter(const float* __restrict__ coor) {
    int id = blockIdx.x * 256 + threadIdx.x;
    if (id >= B_ * N_) return;
    int b = id / N_, n = id % N_;
    const float* cb = coor + b * 3 * N_;
    float x = cb[n], y = cb[N_ + n], z = cb[2 * N_ + n];
    float sq = fmaf(x, x, fmaf(y, y, z * z));   // same chain as query side
    int cx = cell_clamp(x), cy = cell_clamp(y), cz = cell_clamp(z);
    int pos = atomicAdd(&g_cellCur[b * NCELL + (cz * NC + cy) * NC + cx], 1);
    g_pts[b * N_ + pos] = make_float4(x, y, z, sq);
    g_pid[b * N_ + pos] = n;
}

// ---------------------------------------------------------------------------
// F GEMM: F[b][n][d] = feaT[b][n][:] . W_fea[d][:] * scale (pairwise f32x2).
// ---------------------------------------------------------------------------
__global__ __launch_bounds__(256) void fgemm_kernel() {
    __shared__ ull   s_wt[32 * 64];
    __shared__ __align__(16) float sfea[4 * 64];
    const int b  = blockIdx.y, n0 = blockIdx.x * 4;
    const int tid = threadIdx.x;
    const int nl = tid >> 6, d = tid & 63;

    for (int e = tid; e < 32 * 64; e += 256) s_wt[e] = g_WsT2[e];
    sfea[tid] = g_feaT[(b * N_ + n0 + nl) * 64 + d];
    __syncthreads();

    const ull* frow = reinterpret_cast<const ull*>(sfea + nl * 64);
    ull acc = 0ull;
#pragma unroll
    for (int c2 = 0; c2 < 32; c2++)
        FMA2ACC(acc, frow[c2], s_wt[c2 * 64 + d]);
    float lo, hi; unpack2(acc, lo, hi);
    g_F[(b * N_ + n0 + nl) * 64 + d] = lo + hi;
}

// ---------------------------------------------------------------------------
// KNN over the grid: one warp per query, distributed top-32 heap (one slot
// per lane), 27-cell neighborhood with conservative box prune.
// Heap key is the LEXICOGRAPHIC pair (d_bits, idx): top-32 by (d, index) is
// visit-order INVARIANT and identical to an index-order scan with strict '<'
// — i.e. bitwise the same neighbor sets as the linear-scan kernel (and
// jax.lax.top_k's lower-index-first tie-break). Distance values themselves
// use the same fmaf chain as all passing rounds.
// ---------------------------------------------------------------------------
__global__ __launch_bounds__(256) void knn_kernel(const float* __restrict__ coor) {
    const int b    = blockIdx.y;
    const int warp = threadIdx.x >> 5;
    const int lane = threadIdx.x & 31;
    const int q    = blockIdx.x * 8 + warp;

    const float* cb = coor + b * 3 * N_;
    const float qx  = cb[q];
    const float qy  = cb[N_ + q];
    const float qz  = cb[2 * N_ + q];
    const float qsq = fmaf(qx, qx, fmaf(qy, qy, qz * qz));

    // per-lane cell range (27 neighborhood cells on lanes 0..26)
    int s = 0, e = 0;
    {
        int qcx = cell_clamp(qx), qcy = cell_clamp(qy), qcz = cell_clamp(qz);
        if (lane < 27) {
            int cx = qcx + (lane % 3) - 1;
            int cy = qcy + ((lane / 3) % 3) - 1;
            int cz = qcz + (lane / 9) - 1;
            if (cx >= 0 && cx < NC && cy >= 0 && cy < NC && cz >= 0 && cz < NC) {
                // conservative box prune (margin >> fp rounding of d)
                float bx0 = cx * 0.2f, by0 = cy * 0.2f, bz0 = cz * 0.2f;
                float ddx = fmaxf(0.f, fmaxf(bx0 - qx, qx - (bx0 + 0.2f)));
                float ddy = fmaxf(0.f, fmaxf(by0 - qy, qy - (by0 + 0.2f)));
                float ddz = fmaxf(0.f, fmaxf(bz0 - qz, qz - (bz0 + 0.2f)));
                float md = ddx * ddx + ddy * ddy + ddz * ddz;
                if (md <= R2_ + 1e-5f) {
                    int ci = b * (NCELL + 1) + (cz * NC + cy) * NC + cx;
                    s = g_cellStart[ci];
                    e = g_cellStart[ci + 1];
                }
            }
        }
    }

    // per-lane heap slot: (distance bits, idx); warp-max key tracked in
    // (cmd, cmi, maxlane). Initial slots = (+inf, 0).
    unsigned mydb  = 0x7f800000u;   // +inf
    unsigned myidx = 0u;
    unsigned cmd = 0x7f800000u, cmi = 0u;
    int maxlane = 0;

    const float4* pts = g_pts + b * N_;
    const int*    pid = g_pid + b * N_;

#pragma unroll 1
    for (int c = 0; c < 27; c++) {
        int cs = __shfl_sync(0xffffffffu, s, c);
        int ce = __shfl_sync(0xffffffffu, e, c);
        for (int i0 = cs; i0 < ce; i0 += 32) {
            int i = i0 + lane;
            bool act = i < ce;
            float4 p = act ? pts[i]
                           : make_float4(0.f, 0.f, 0.f, __int_as_float(0x7f800000));
            float dot = fmaf(qx, p.x, fmaf(qy, p.y, qz * p.z));
            float d   = fmaf(-2.f, dot, qsq + p.w);
            d = fmaxf(d, 0.f);   // keep float-as-uint compare monotonic
            unsigned db = __float_as_uint(d);
            unsigned pv = act ? (unsigned)pid[i] : 0u;
            bool ok = act && (d <= R2_) &&
                      (db < cmd || (db == cmd && pv < cmi));
            unsigned mask = __ballot_sync(0xffffffffu, ok);
            while (mask) {
                int j = __ffs(mask) - 1;
                mask &= mask - 1;
                unsigned djb = __shfl_sync(0xffffffffu, db, j);
                unsigned cj  = __shfl_sync(0xffffffffu, pv, j);
                if (djb < cmd || (djb == cmd && cj < cmi)) {   // warp-uniform
                    if (lane == maxlane) { mydb = djb; myidx = cj; }
                    cmd = __reduce_max_sync(0xffffffffu, mydb);
                    bool eq = (mydb == cmd);
                    cmi = __reduce_max_sync(0xffffffffu, eq ? myidx : 0u);
                    maxlane = __ffs(__ballot_sync(0xffffffffu,
                                        eq && (myidx == cmi))) - 1;
                }
            }
        }
    }
    float myd = __uint_as_float(mydb);
    int finalIdx = (myd <= R2_) ? (int)myidx : q;
    g_gidx[(b * N_ + q) * K_ + lane] = finalIdx;
}

// ---------------------------------------------------------------------------
// Aggregation: y[q,k,d] = F[id_k][d] + gcoor.Wc[d] + bias[d]; ReLU+max over k.
// ---------------------------------------------------------------------------
__global__ __launch_bounds__(256) void agg_kernel(const float* __restrict__ coor,
                                                  float* __restrict__ out) {
    __shared__ int   sIdx[4 * 32];
    __shared__ float scx[4 * 32], scy[4 * 32], scz[4 * 32];
    __shared__ float sout[4 * 64];

    const int b   = blockIdx.y;
    const int q0  = blockIdx.x * 4;
    const int tid = threadIdx.x;
    const int q   = tid >> 6, d = tid & 63;
    const float* cb = coor + b * 3 * N_;

    if (tid < 128) {
        int qq = tid >> 5, k = tid & 31;
        int id = g_gidx[(b * N_ + q0 + qq) * K_ + k];
        sIdx[tid] = id;
        scx[tid] = (cb[id] - cb[q0 + qq]) * 5.0f;                 // /RADIUS
        scy[tid] = (cb[N_ + id] - cb[N_ + q0 + qq]) * 5.0f;
        scz[tid] = (cb[2 * N_ + id] - cb[2 * N_ + q0 + qq]) * 5.0f;
    }
    __syncthreads();

    const float wx = g_Wc[d], wy = g_Wc[64 + d], wz = g_Wc[128 + d];
    const float bia = g_bias[d];
    const float* Fb = g_F + (size_t)(b * N_) * 64;

    float m = 0.f;  // ReLU identity
#pragma unroll 4
    for (int k = 0; k < 32; k++) {
        int id = sIdx[q * 32 + k];
        float f = __ldg(Fb + id * 64 + d);
        float y = fmaf(scx[q * 32 + k], wx, f);
        y = fmaf(scy[q * 32 + k], wy, y);
        y = fmaf(scz[q * 32 + k], wz, y);
        m = fmaxf(m, y + bia);
    }
    sout[q * 64 + d] = m;
    __syncthreads();

    int d2 = tid >> 2, q2 = tid & 3;
    out[(b * 64 + d2) * N_ + q0 + q2] = sout[q2 * 64 + d2];
}

// ---------------------------------------------------------------------------
extern "C" void kernel_launch(void* const* d_in, const int* in_sizes, int n_in,
                              void* d_out, int out_size) {
    const float* coor  = (const float*)d_in[0];
    const float* fea   = (const float*)d_in[1];
    const float* W     = (const float*)d_in[2];
    const float* gamma = (const float*)d_in[3];
    const float* beta  = (const float*)d_in[4];
    const float* rmean = (const float*)d_in[5];
    const float* rvar  = (const float*)d_in[6];
    float* out = (float*)d_out;

    prep_kernel<<<B_ * 2 * 256 + 1, 256>>>(fea, W, gamma, beta, rmean, rvar);
    grid_count<<<(B_ * N_ + 255) / 256, 256>>>(coor);
    grid_scan<<<1, 128>>>();
    grid_scatter<<<(B_ * N_ + 255) / 256, 256>>>(coor);
    fgemm_kernel<<<dim3(N_ / 4, B_), 256>>>();
    knn_kernel<<<dim3(N_ / 8, B_), 256>>>(coor);
    agg_kernel<<<dim3(N_ / 4, B_), 256>>>(coor, out);
}

// round 9
// speedup vs baseline: 4.3105x; 1.3922x over previous
#include <cuda_runtime.h>

#define B_ 4
#define C_ 64
#define N_ 8192
#define K_ 32
#define R2_ 0.04f
#define BN_EPS_ 1e-5f
#define NC 5
#define NCELL (NC * NC * NC)
#define INFB 0x7f800000u

typedef unsigned long long ull;

#define FMA2ACC(acc, a, bb) asm("fma.rn.f32x2 %0, %1, %2, %0;" : "+l"(acc) : "l"(a), "l"(bb))

__device__ __forceinline__ ull pack2(float lo, float hi) {
    ull r; asm("mov.b64 %0, {%1, %2};" : "=l"(r) : "f"(lo), "f"(hi)); return r;
}
__device__ __forceinline__ void unpack2(ull v, float& lo, float& hi) {
    asm("mov.b64 {%0, %1}, %2;" : "=f"(lo), "=f"(hi) : "l"(v));
}
__device__ __forceinline__ int cell_clamp(float v) {
    int c = (int)(v * 5.0f);
    return min(NC - 1, max(0, c));
}

// Scratch (static __device__ arrays — no allocation)
__device__ float  g_feaT[B_ * N_ * C_];   // (B, N, C) transposed features
__device__ float  g_F[B_ * N_ * C_];      // F[b][n][d] = fea row . W_fea[d] * scale
__device__ int    g_gidx[B_ * N_ * K_];   // final (masked) neighbor indices
__device__ ull    g_WsT2[32 * 64];        // packed (w[2c],w[2c+1]) per d, BN-scaled
__device__ float  g_Wc[3 * 64];           // coord weights * scale
__device__ float  g_bias[64];             // BN-folded bias
// grid structures
__device__ int    g_cnt[B_ * NCELL];      // zeroed by grid_scan after use
__device__ int    g_cellStart[B_ * (NCELL + 1)];
__device__ int    g_rank[B_ * N_];        // intra-cell rank per point
__device__ float4 g_pts[B_ * N_];         // cell-sorted (x,y,z,sq)
__device__ int    g_pid[B_ * N_];         // original point index

#define NBLK_T (B_ * 2 * 256)   // 2048 transpose blocks (b = bid>>9 covers 0..3)

// ---------------------------------------------------------------------------
// K1 (fused): transpose blocks [0,2048) + W-fold block [2048] + count blocks
// [2049,2177). Count records each point's intra-cell rank (atomic return) so
// scatter needs no atomics. Intra-cell point order is nondeterministic but
// the KNN selection key (d_bits, idx) is visit-order invariant => output
// deterministic.  (R8 bug: transpose range was 1024 -> batches 2,3 never
// transposed.)
// ---------------------------------------------------------------------------
__global__ __launch_bounds__(256) void k_prep(
    const float* __restrict__ coor, const float* __restrict__ fea,
    const float* __restrict__ W,
    const float* __restrict__ gamma_, const float* __restrict__ beta_,
    const float* __restrict__ rmean, const float* __restrict__ rvar)
{
    const int bid = blockIdx.x;
    const int tid = threadIdx.x;
    if (bid < NBLK_T) {
        // ---- tiled transpose (B,C,N)->(B,N,C) ----
        __shared__ float t[32][33];
        const int nblk = bid & 255;
        const int cblk = (bid >> 8) & 1;
        const int b    = bid >> 9;
        const int lane = tid & 31, w = tid >> 5;
        const int c0 = cblk * 32, n0 = nblk * 32;
        const float* src = fea + (b * 64 + c0) * N_ + n0;
#pragma unroll
        for (int i = w; i < 32; i += 8) t[i][lane] = src[i * N_ + lane];
        __syncthreads();
        float* dst = g_feaT + (b * N_ + n0) * 64 + c0;
#pragma unroll
        for (int i = w; i < 32; i += 8) dst[i * 64 + lane] = t[lane][i];
    } else if (bid == NBLK_T) {
        // ---- BN fold into W ----
        if (tid < 64) {
            float sc = gamma_[tid] * rsqrtf(rvar[tid] + BN_EPS_);
            g_bias[tid] = beta_[tid] - rmean[tid] * sc;
            g_Wc[tid]       = W[tid * 67 + 64] * sc;
            g_Wc[64 + tid]  = W[tid * 67 + 65] * sc;
            g_Wc[128 + tid] = W[tid * 67 + 66] * sc;
        }
        for (int e = tid; e < 32 * 64; e += 256) {
            int c2 = e >> 6, d = e & 63;
            float sc = gamma_[d] * rsqrtf(rvar[d] + BN_EPS_);
            g_WsT2[e] = pack2(W[d * 67 + 2 * c2] * sc, W[d * 67 + 2 * c2 + 1] * sc);
        }
    } else {
        // ---- grid count + rank ----
        int id = (bid - (NBLK_T + 1)) * 256 + tid;
        int b = id / N_, n = id % N_;
        const float* cb = coor + b * 3 * N_;
        int cx = cell_clamp(cb[n]);
        int cy = cell_clamp(cb[N_ + n]);
        int cz = cell_clamp(cb[2 * N_ + n]);
        g_rank[id] = atomicAdd(&g_cnt[b * NCELL + (cz * NC + cy) * NC + cx], 1);
    }
}

// ---------------------------------------------------------------------------
// Scan: exclusive prefix per batch (one warp per batch), then zero g_cnt for
// the next graph replay.
// ---------------------------------------------------------------------------
__global__ void grid_scan() {
    int wb = threadIdx.x >> 5;
    int lane = threadIdx.x & 31;
    if (wb >= B_) return;
    if (lane == 0) g_cellStart[wb * (NCELL + 1)] = 0;
    int carry = 0;
    for (int c0 = 0; c0 < NCELL; c0 += 32) {
        int i = c0 + lane;
        int orig = (i < NCELL) ? g_cnt[wb * NCELL + i] : 0;
        int v = orig;
#pragma unroll
        for (int o = 1; o < 32; o <<= 1) {
            int tv = __shfl_up_sync(0xffffffffu, v, o);
            if (lane >= o) v += tv;
        }
        if (i < NCELL) g_cellStart[wb * (NCELL + 1) + i + 1] = carry + v;
        carry += __shfl_sync(0xffffffffu, v, 31);
    }
    for (int i = lane; i < NCELL; i += 32) g_cnt[wb * NCELL + i] = 0;
}

// ---------------------------------------------------------------------------
// Scatter (atomic-free): pos = cellStart[cell] + rank.
// ---------------------------------------------------------------------------
__global__ __launch_bounds__(256) void grid_scatter(const float* __restrict__ coor) {
    int id = blockIdx.x * 256 + threadIdx.x;
    int b = id / N_, n = id % N_;
    const float* cb = coor + b * 3 * N_;
    float x = cb[n], y = cb[N_ + n], z = cb[2 * N_ + n];
    float sq = fmaf(x, x, fmaf(y, y, z * z));   // same chain as query side
    int cx = cell_clamp(x), cy = cell_clamp(y), cz = cell_clamp(z);
    int pos = g_cellStart[b * (NCELL + 1) + (cz * NC + cy) * NC + cx] + g_rank[id];
    g_pts[b * N_ + pos] = make_float4(x, y, z, sq);
    g_pid[b * N_ + pos] = n;
}

// ---------------------------------------------------------------------------
// F GEMM: F[b][n][d] = feaT[b][n][:] . W_fea[d][:] * scale (pairwise f32x2).
// ---------------------------------------------------------------------------
__global__ __launch_bounds__(256) void fgemm_kernel() {
    __shared__ ull   s_wt[32 * 64];
    __shared__ __align__(16) float sfea[4 * 64];
    const int b  = blockIdx.y, n0 = blockIdx.x * 4;
    const int tid = threadIdx.x;
    const int nl = tid >> 6, d = tid & 63;

    for (int e = tid; e < 32 * 64; e += 256) s_wt[e] = g_WsT2[e];
    sfea[tid] = g_feaT[(b * N_ + n0 + nl) * 64 + d];
    __syncthreads();

    const ull* frow = reinterpret_cast<const ull*>(sfea + nl * 64);
    ull acc = 0ull;
#pragma unroll
    for (int c2 = 0; c2 < 32; c2++)
        FMA2ACC(acc, frow[c2], s_wt[c2 * 64 + d]);
    float lo, hi; unpack2(acc, lo, hi);
    g_F[(b * N_ + n0 + nl) * 64 + d] = lo + hi;
}

// ---------------------------------------------------------------------------
// KNN: one warp per query, distributed top-32 heap keyed on the lexicographic
// pair (d_bits, idx) — visit-order invariant. Cells visited in increasing
// box-min-distance order; once the heap is full and curmax + 4e-6 < md of all
// remaining cells, no remaining candidate can qualify => break with the exact
// same selected set.
// ---------------------------------------------------------------------------
__global__ __launch_bounds__(256) void knn_kernel(const float* __restrict__ coor) {
    const int b    = blockIdx.y;
    const int warp = threadIdx.x >> 5;
    const int lane = threadIdx.x & 31;
    const int q    = blockIdx.x * 8 + warp;

    const float* cb = coor + b * 3 * N_;
    const float qx  = cb[q];
    const float qy  = cb[N_ + q];
    const float qz  = cb[2 * N_ + q];
    const float qsq = fmaf(qx, qx, fmaf(qy, qy, qz * qz));

    // per-lane cell range + box min-dist (27 neighborhood cells on lanes 0..26)
    int s = 0, e = 0;
    unsigned mdu = INFB;
    {
        int qcx = cell_clamp(qx), qcy = cell_clamp(qy), qcz = cell_clamp(qz);
        if (lane < 27) {
            int cx = qcx + (lane % 3) - 1;
            int cy = qcy + ((lane / 3) % 3) - 1;
            int cz = qcz + (lane / 9) - 1;
            if (cx >= 0 && cx < NC && cy >= 0 && cy < NC && cz >= 0 && cz < NC) {
                float bx0 = cx * 0.2f, by0 = cy * 0.2f, bz0 = cz * 0.2f;
                float ddx = fmaxf(0.f, fmaxf(bx0 - qx, qx - (bx0 + 0.2f)));
                float ddy = fmaxf(0.f, fmaxf(by0 - qy, qy - (by0 + 0.2f)));
                float ddz = fmaxf(0.f, fmaxf(bz0 - qz, qz - (bz0 + 0.2f)));
                float md = ddx * ddx + ddy * ddy + ddz * ddz;
                if (md <= R2_ + 1e-5f) {
                    int ci = b * (NCELL + 1) + (cz * NC + cy) * NC + cx;
                    s = g_cellStart[ci];
                    e = g_cellStart[ci + 1];
                    mdu = __float_as_uint(md);
                }
            }
        }
    }

    unsigned mydb  = INFB;   // per-lane heap slot (distance bits)
    unsigned myidx = 0u;
    unsigned cmd = INFB, cmi = 0u;  // warp-max key
    int maxlane = 0;

    const float4* pts = g_pts + b * N_;
    const int*    pid = g_pid + b * N_;

#pragma unroll 1
    for (int r = 0; r < 27; r++) {
        unsigned rmin = __reduce_min_sync(0xffffffffu, mdu);
        if (rmin == INFB) break;                                   // no cells left
        if (__uint_as_float(cmd) + 4e-6f < __uint_as_float(rmin))  // heap full &
            break;                                                 // provably done
        int j = __ffs(__ballot_sync(0xffffffffu, mdu == rmin)) - 1;
        int cs = __shfl_sync(0xffffffffu, s, j);
        int ce = __shfl_sync(0xffffffffu, e, j);
        if (lane == j) mdu = INFB;

        for (int i0 = cs; i0 < ce; i0 += 32) {
            int i = i0 + lane;
            bool act = i < ce;
            float4 p = act ? pts[i]
                           : make_float4(0.f, 0.f, 0.f, __int_as_float(0x7f800000));
            float dot = fmaf(qx, p.x, fmaf(qy, p.y, qz * p.z));
            float d   = fmaf(-2.f, dot, qsq + p.w);
            d = fmaxf(d, 0.f);   // keep float-as-uint compare monotonic
            unsigned db = __float_as_uint(d);
            unsigned pv = act ? (unsigned)pid[i] : 0u;
            bool ok = act && (d <= R2_) &&
                      (db < cmd || (db == cmd && pv < cmi));
            unsigned mask = __ballot_sync(0xffffffffu, ok);
            while (mask) {
                int jj = __ffs(mask) - 1;
                mask &= mask - 1;
                unsigned djb = __shfl_sync(0xffffffffu, db, jj);
                unsigned cj  = __shfl_sync(0xffffffffu, pv, jj);
                if (djb < cmd || (djb == cmd && cj < cmi)) {   // warp-uniform
                    if (lane == maxlane) { mydb = djb; myidx = cj; }
                    cmd = __reduce_max_sync(0xffffffffu, mydb);
                    bool eq = (mydb == cmd);
                    cmi = __reduce_max_sync(0xffffffffu, eq ? myidx : 0u);
                    maxlane = __ffs(__ballot_sync(0xffffffffu,
                                        eq && (myidx == cmi))) - 1;
                }
            }
        }
    }
    int finalIdx = (__uint_as_float(mydb) <= R2_) ? (int)myidx : q;
    g_gidx[(b * N_ + q) * K_ + lane] = finalIdx;
}

// ---------------------------------------------------------------------------
// Aggregation: warp = one query (64 d's, 2 per lane via f32x2).
// y[q,k,d] = F[id_k][d] + gcoor.Wc[d]; m = max_k y; out = relu(m + bias)
// (bias hoist is bitwise-identical: constant add is monotone).
// ---------------------------------------------------------------------------
__global__ __launch_bounds__(128) void agg_kernel(const float* __restrict__ coor,
                                                  float* __restrict__ out) {
    __shared__ __align__(16) float4 scc[4 * 32];   // (cx,cy,cz,idx_bits) per (q,k)
    __shared__ float sout[4 * 64];

    const int b    = blockIdx.y;
    const int q0   = blockIdx.x * 4;
    const int tid  = threadIdx.x;
    const int q    = tid >> 5;        // warp = query
    const int lane = tid & 31;
    const float* cb = coor + b * 3 * N_;

    {   // stage coords + idx (all 128 threads, one (q,k) each)
        int id = g_gidx[(b * N_ + q0 + q) * K_ + lane];
        scc[tid] = make_float4((cb[id] - cb[q0 + q]) * 5.0f,
                               (cb[N_ + id] - cb[N_ + q0 + q]) * 5.0f,
                               (cb[2 * N_ + id] - cb[2 * N_ + q0 + q]) * 5.0f,
                               __int_as_float(id));
    }
    __syncthreads();

    const ull wx2 = reinterpret_cast<const ull*>(g_Wc)[lane];
    const ull wy2 = reinterpret_cast<const ull*>(g_Wc + 64)[lane];
    const ull wz2 = reinterpret_cast<const ull*>(g_Wc + 128)[lane];
    const float2 bb = reinterpret_cast<const float2*>(g_bias)[lane];
    const float* Fb = g_F + (size_t)(b * N_) * 64;

    float m0 = __int_as_float(0xff800000), m1 = m0;   // -inf
#pragma unroll 4
    for (int k = 0; k < 32; k++) {
        float4 cc = scc[q * 32 + k];                   // broadcast LDS.128
        int id = __float_as_int(cc.w);
        ull y = reinterpret_cast<const ull*>(Fb + id * 64)[lane];  // LDG.64
        FMA2ACC(y, pack2(cc.x, cc.x), wx2);
        FMA2ACC(y, pack2(cc.y, cc.y), wy2);
        FMA2ACC(y, pack2(cc.z, cc.z), wz2);
        float y0, y1; unpack2(y, y0, y1);
        m0 = fmaxf(m0, y0);
        m1 = fmaxf(m1, y1);
    }
    sout[q * 64 + 2 * lane]     = fmaxf(m0 + bb.x, 0.f);
    sout[q * 64 + 2 * lane + 1] = fmaxf(m1 + bb.y, 0.f);
    __syncthreads();

    if (tid < 64) {   // transposed store: 4 consecutive n's per d row
        float4 v = make_float4(sout[tid], sout[64 + tid],
                               sout[128 + tid], sout[192 + tid]);
        *reinterpret_cast<float4*>(&out[(b * 64 + tid) * N_ + q0]) = v;
    }
}

// ---------------------------------------------------------------------------
extern "C" void kernel_launch(void* const* d_in, const int* in_sizes, int n_in,
                              void* d_out, int out_size) {
    const float* coor  = (const float*)d_in[0];
    const float* fea   = (const float*)d_in[1];
    const float* W     = (const float*)d_in[2];
    const float* gamma = (const float*)d_in[3];
    const float* beta  = (const float*)d_in[4];
    const float* rmean = (const float*)d_in[5];
    const float* rvar  = (const float*)d_in[6];
    float* out = (float*)d_out;

    k_prep<<<NBLK_T + 1 + B_ * N_ / 256, 256>>>(coor, fea, W,
                                                gamma, beta, rmean, rvar);
    grid_scan<<<1, 128>>>();
    grid_scatter<<<B_ * N_ / 256, 256>>>(coor);
    fgemm_kernel<<<dim3(N_ / 4, B_), 256>>>();
    knn_kernel<<<dim3(N_ / 8, B_), 256>>>(coor);
    agg_kernel<<<dim3(N_ / 4, B_), 128>>>(coor, out);
}

// round 10
// speedup vs baseline: 4.7873x; 1.1106x over previous
#include <cuda_runtime.h>

#define B_ 4
#define C_ 64
#define N_ 8192
#define K_ 32
#define R2_ 0.04f
#define BN_EPS_ 1e-5f
#define NC 5
#define NCELL (NC * NC * NC)
#define INFB 0x7f800000u

typedef unsigned long long ull;

#define FMA2ACC(acc, a, bb) asm("fma.rn.f32x2 %0, %1, %2, %0;" : "+l"(acc) : "l"(a), "l"(bb))

__device__ __forceinline__ ull pack2(float lo, float hi) {
    ull r; asm("mov.b64 %0, {%1, %2};" : "=l"(r) : "f"(lo), "f"(hi)); return r;
}
__device__ __forceinline__ void unpack2(ull v, float& lo, float& hi) {
    asm("mov.b64 {%0, %1}, %2;" : "=f"(lo), "=f"(hi) : "l"(v));
}
__device__ __forceinline__ int cell_clamp(float v) {
    int c = (int)(v * 5.0f);
    return min(NC - 1, max(0, c));
}

// Scratch (static __device__ arrays — no allocation)
__device__ float  g_F[B_ * N_ * C_];      // F[b][n][d] = fea row . W_fea[d] * scale
__device__ int    g_gidx[B_ * N_ * K_];   // final (masked) neighbor indices
__device__ ull    g_WsT2[32 * 64];        // packed (w[2c],w[2c+1]) per d, BN-scaled
__device__ float  g_Wc[3 * 64];           // coord weights * scale
__device__ float  g_bias[64];             // BN-folded bias
// grid structures
__device__ int    g_cnt[B_ * NCELL];      // zeroed by grid_scan after use
__device__ int    g_cellStart[B_ * (NCELL + 1)];
__device__ int    g_rank[B_ * N_];        // intra-cell rank per point
__device__ float4 g_pts[B_ * N_];         // cell-sorted (x,y,z,sq)
__device__ int    g_pid[B_ * N_];         // original point index

// ---------------------------------------------------------------------------
// K1: W-fold block [0] + grid count blocks [1,129). Count records each
// point's intra-cell rank (atomic return) so scatter needs no atomics.
// Intra-cell order is nondeterministic but the KNN selection key
// (d_bits, idx) is visit-order invariant => output deterministic.
// (The old transpose stage is gone: fgemm now reads fea directly.)
// ---------------------------------------------------------------------------
__global__ __launch_bounds__(256) void k_prep(
    const float* __restrict__ coor,
    const float* __restrict__ W,
    const float* __restrict__ gamma_, const float* __restrict__ beta_,
    const float* __restrict__ rmean, const float* __restrict__ rvar)
{
    const int bid = blockIdx.x;
    const int tid = threadIdx.x;
    if (bid == 0) {
        // ---- BN fold into W ----
        if (tid < 64) {
            float sc = gamma_[tid] * rsqrtf(rvar[tid] + BN_EPS_);
            g_bias[tid] = beta_[tid] - rmean[tid] * sc;
            g_Wc[tid]       = W[tid * 67 + 64] * sc;
            g_Wc[64 + tid]  = W[tid * 67 + 65] * sc;
            g_Wc[128 + tid] = W[tid * 67 + 66] * sc;
        }
        for (int e = tid; e < 32 * 64; e += 256) {
            int c2 = e >> 6, d = e & 63;
            float sc = gamma_[d] * rsqrtf(rvar[d] + BN_EPS_);
            g_WsT2[e] = pack2(W[d * 67 + 2 * c2] * sc, W[d * 67 + 2 * c2 + 1] * sc);
        }
    } else {
        // ---- grid count + rank ----
        int id = (bid - 1) * 256 + tid;
        int b = id / N_, n = id % N_;
        const float* cb = coor + b * 3 * N_;
        int cx = cell_clamp(cb[n]);
        int cy = cell_clamp(cb[N_ + n]);
        int cz = cell_clamp(cb[2 * N_ + n]);
        g_rank[id] = atomicAdd(&g_cnt[b * NCELL + (cz * NC + cy) * NC + cx], 1);
    }
}

// ---------------------------------------------------------------------------
// Scan: exclusive prefix per batch (one warp per batch), then zero g_cnt for
// the next graph replay.
// ---------------------------------------------------------------------------
__global__ void grid_scan() {
    int wb = threadIdx.x >> 5;
    int lane = threadIdx.x & 31;
    if (wb >= B_) return;
    if (lane == 0) g_cellStart[wb * (NCELL + 1)] = 0;
    int carry = 0;
    for (int c0 = 0; c0 < NCELL; c0 += 32) {
        int i = c0 + lane;
        int orig = (i < NCELL) ? g_cnt[wb * NCELL + i] : 0;
        int v = orig;
#pragma unroll
        for (int o = 1; o < 32; o <<= 1) {
            int tv = __shfl_up_sync(0xffffffffu, v, o);
            if (lane >= o) v += tv;
        }
        if (i < NCELL) g_cellStart[wb * (NCELL + 1) + i + 1] = carry + v;
        carry += __shfl_sync(0xffffffffu, v, 31);
    }
    for (int i = lane; i < NCELL; i += 32) g_cnt[wb * NCELL + i] = 0;
}

// ---------------------------------------------------------------------------
// Scatter (atomic-free): pos = cellStart[cell] + rank.
// ---------------------------------------------------------------------------
__global__ __launch_bounds__(256) void grid_scatter(const float* __restrict__ coor) {
    int id = blockIdx.x * 256 + threadIdx.x;
    int b = id / N_, n = id % N_;
    const float* cb = coor + b * 3 * N_;
    float x = cb[n], y = cb[N_ + n], z = cb[2 * N_ + n];
    float sq = fmaf(x, x, fmaf(y, y, z * z));   // same chain as query side
    int cx = cell_clamp(x), cy = cell_clamp(y), cz = cell_clamp(z);
    int pos = g_cellStart[b * (NCELL + 1) + (cz * NC + cy) * NC + cx] + g_rank[id];
    g_pts[b * N_ + pos] = make_float4(x, y, z, sq);
    g_pid[b * N_ + pos] = n;
}

// ---------------------------------------------------------------------------
// F GEMM (re-tiled): block = 256 threads, 32 n's. Reads fea in native (B,C,N)
// layout (coalesced 128B rows) and transposes into padded shared — the old
// standalone transpose kernel is gone. Warp = 8 d's x 32 n's (lane = n),
// 8 outputs/thread: per c2-step 1 per-lane fea LDS.64 + 4 broadcast ull2
// weight loads feed 8 FMA2 — ~3x fewer shared wavefronts per output.
// F value chain bit-identical: FMA2 over c2=0..31 sequential, then lo+hi.
// ---------------------------------------------------------------------------
__global__ __launch_bounds__(256) void fgemm_kernel(const float* __restrict__ fea) {
    __shared__ ull s_wt[32 * 64];                       // [c2][d]  16 KB
    __shared__ __align__(16) float sfea[32 * 66];       // [n][c] padded
    const int b   = blockIdx.y, n0 = blockIdx.x * 32;
    const int tid = threadIdx.x;
    const int w   = tid >> 5, lane = tid & 31;

    for (int e = tid; e < 32 * 64; e += 256) s_wt[e] = g_WsT2[e];
#pragma unroll
    for (int i = 0; i < 8; i++) {
        int c = w * 8 + i;
        sfea[lane * 66 + c] = fea[(b * 64 + c) * N_ + n0 + lane];
    }
    __syncthreads();

    const ull* frow = reinterpret_cast<const ull*>(sfea + lane * 66);
    const int d0 = w * 8;
    ull acc[8];
#pragma unroll
    for (int j = 0; j < 8; j++) acc[j] = 0ull;
#pragma unroll 8
    for (int c2 = 0; c2 < 32; c2++) {
        ull f = frow[c2];
        const ull* wr = s_wt + c2 * 64 + d0;
        ulonglong2 w01 = *reinterpret_cast<const ulonglong2*>(wr);
        ulonglong2 w23 = *reinterpret_cast<const ulonglong2*>(wr + 2);
        ulonglong2 w45 = *reinterpret_cast<const ulonglong2*>(wr + 4);
        ulonglong2 w67 = *reinterpret_cast<const ulonglong2*>(wr + 6);
        FMA2ACC(acc[0], f, w01.x); FMA2ACC(acc[1], f, w01.y);
        FMA2ACC(acc[2], f, w23.x); FMA2ACC(acc[3], f, w23.y);
        FMA2ACC(acc[4], f, w45.x); FMA2ACC(acc[5], f, w45.y);
        FMA2ACC(acc[6], f, w67.x); FMA2ACC(acc[7], f, w67.y);
    }
    float o[8];
#pragma unroll
    for (int j = 0; j < 8; j++) {
        float lo, hi; unpack2(acc[j], lo, hi);
        o[j] = lo + hi;
    }
    float4* dst = reinterpret_cast<float4*>(
        g_F + ((size_t)(b * N_ + n0 + lane)) * 64 + d0);
    dst[0] = make_float4(o[0], o[1], o[2], o[3]);
    dst[1] = make_float4(o[4], o[5], o[6], o[7]);
}

// ---------------------------------------------------------------------------
// KNN: one warp per query, distributed top-32 heap keyed on the lexicographic
// pair (d_bits, idx) — visit-order invariant. Cells visited in increasing
// box-min-distance order; once the heap is full and curmax + 4e-6 < md of all
// remaining cells, no remaining candidate can qualify => break with the exact
// same selected set.  (UNCHANGED from R9 — bit-identical.)
// ---------------------------------------------------------------------------
__global__ __launch_bounds__(256) void knn_kernel(const float* __restrict__ coor) {
    const int b    = blockIdx.y;
    const int warp = threadIdx.x >> 5;
    const int lane = threadIdx.x & 31;
    const int q    = blockIdx.x * 8 + warp;

    const float* cb = coor + b * 3 * N_;
    const float qx  = cb[q];
    const float qy  = cb[N_ + q];
    const float qz  = cb[2 * N_ + q];
    const float qsq = fmaf(qx, qx, fmaf(qy, qy, qz * qz));

    int s = 0, e = 0;
    unsigned mdu = INFB;
    {
        int qcx = cell_clamp(qx), qcy = cell_clamp(qy), qcz = cell_clamp(qz);
        if (lane < 27) {
            int cx = qcx + (lane % 3) - 1;
            int cy = qcy + ((lane / 3) % 3) - 1;
            int cz = qcz + (lane / 9) - 1;
            if (cx >= 0 && cx < NC && cy >= 0 && cy < NC && cz >= 0 && cz < NC) {
                float bx0 = cx * 0.2f, by0 = cy * 0.2f, bz0 = cz * 0.2f;
                float ddx = fmaxf(0.f, fmaxf(bx0 - qx, qx - (bx0 + 0.2f)));
                float ddy = fmaxf(0.f, fmaxf(by0 - qy, qy - (by0 + 0.2f)));
                float ddz = fmaxf(0.f, fmaxf(bz0 - qz, qz - (bz0 + 0.2f)));
                float md = ddx * ddx + ddy * ddy + ddz * ddz;
                if (md <= R2_ + 1e-5f) {
                    int ci = b * (NCELL + 1) + (cz * NC + cy) * NC + cx;
                    s = g_cellStart[ci];
                    e = g_cellStart[ci + 1];
                    mdu = __float_as_uint(md);
                }
            }
        }
    }

    unsigned mydb  = INFB;
    unsigned myidx = 0u;
    unsigned cmd = INFB, cmi = 0u;
    int maxlane = 0;

    const float4* pts = g_pts + b * N_;
    const int*    pid = g_pid + b * N_;

#pragma unroll 1
    for (int r = 0; r < 27; r++) {
        unsigned rmin = __reduce_min_sync(0xffffffffu, mdu);
        if (rmin == INFB) break;
        if (__uint_as_float(cmd) + 4e-6f < __uint_as_float(rmin)) break;
        int j = __ffs(__ballot_sync(0xffffffffu, mdu == rmin)) - 1;
        int cs = __shfl_sync(0xffffffffu, s, j);
        int ce = __shfl_sync(0xffffffffu, e, j);
        if (lane == j) mdu = INFB;

        for (int i0 = cs; i0 < ce; i0 += 32) {
            int i = i0 + lane;
            bool act = i < ce;
            float4 p = act ? pts[i]
                           : make_float4(0.f, 0.f, 0.f, __int_as_float(0x7f800000));
            float dot = fmaf(qx, p.x, fmaf(qy, p.y, qz * p.z));
            float d   = fmaf(-2.f, dot, qsq + p.w);
            d = fmaxf(d, 0.f);
            unsigned db = __float_as_uint(d);
            unsigned pv = act ? (unsigned)pid[i] : 0u;
            bool ok = act && (d <= R2_) &&
                      (db < cmd || (db == cmd && pv < cmi));
            unsigned mask = __ballot_sync(0xffffffffu, ok);
            while (mask) {
                int jj = __ffs(mask) - 1;
                mask &= mask - 1;
                unsigned djb = __shfl_sync(0xffffffffu, db, jj);
                unsigned cj  = __shfl_sync(0xffffffffu, pv, jj);
                if (djb < cmd || (djb == cmd && cj < cmi)) {
                    if (lane == maxlane) { mydb = djb; myidx = cj; }
                    cmd = __reduce_max_sync(0xffffffffu, mydb);
                    bool eq = (mydb == cmd);
                    cmi = __reduce_max_sync(0xffffffffu, eq ? myidx : 0u);
                    maxlane = __ffs(__ballot_sync(0xffffffffu,
                                        eq && (myidx == cmi))) - 1;
                }
            }
        }
    }
    int finalIdx = (__uint_as_float(mydb) <= R2_) ? (int)myidx : q;
    g_gidx[(b * N_ + q) * K_ + lane] = finalIdx;
}

// ---------------------------------------------------------------------------
// Aggregation: warp = one query (64 d's, 2 per lane via f32x2).  (UNCHANGED)
// ---------------------------------------------------------------------------
__global__ __launch_bounds__(128) void agg_kernel(const float* __restrict__ coor,
                                                  float* __restrict__ out) {
    __shared__ __align__(16) float4 scc[4 * 32];
    __shared__ float sout[4 * 64];

    const int b    = blockIdx.y;
    const int q0   = blockIdx.x * 4;
    const int tid  = threadIdx.x;
    const int q    = tid >> 5;
    const int lane = tid & 31;
    const float* cb = coor + b * 3 * N_;

    {
        int id = g_gidx[(b * N_ + q0 + q) * K_ + lane];
        scc[tid] = make_float4((cb[id] - cb[q0 + q]) * 5.0f,
                               (cb[N_ + id] - cb[N_ + q0 + q]) * 5.0f,
                               (cb[2 * N_ + id] - cb[2 * N_ + q0 + q]) * 5.0f,
                               __int_as_float(id));
    }
    __syncthreads();

    const ull wx2 = reinterpret_cast<const ull*>(g_Wc)[lane];
    const ull wy2 = reinterpret_cast<const ull*>(g_Wc + 64)[lane];
    const ull wz2 = reinterpret_cast<const ull*>(g_Wc + 128)[lane];
    const float2 bb = reinterpret_cast<const float2*>(g_bias)[lane];
    const float* Fb = g_F + (size_t)(b * N_) * 64;

    float m0 = __int_as_float(0xff800000), m1 = m0;
#pragma unroll 4
    for (int k = 0; k < 32; k++) {
        float4 cc = scc[q * 32 + k];
        int id = __float_as_int(cc.w);
        ull y = reinterpret_cast<const ull*>(Fb + id * 64)[lane];
        FMA2ACC(y, pack2(cc.x, cc.x), wx2);
        FMA2ACC(y, pack2(cc.y, cc.y), wy2);
        FMA2ACC(y, pack2(cc.z, cc.z), wz2);
        float y0, y1; unpack2(y, y0, y1);
        m0 = fmaxf(m0, y0);
        m1 = fmaxf(m1, y1);
    }
    sout[q * 64 + 2 * lane]     = fmaxf(m0 + bb.x, 0.f);
    sout[q * 64 + 2 * lane + 1] = fmaxf(m1 + bb.y, 0.f);
    __syncthreads();

    if (tid < 64) {
        float4 v = make_float4(sout[tid], sout[64 + tid],
                               sout[128 + tid], sout[192 + tid]);
        *reinterpret_cast<float4*>(&out[(b * 64 + tid) * N_ + q0]) = v;
    }
}

// ---------------------------------------------------------------------------
extern "C" void kernel_launch(void* const* d_in, const int* in_sizes, int n_in,
                              void* d_out, int out_size) {
    const float* coor  = (const float*)d_in[0];
    const float* fea   = (const float*)d_in[1];
    const float* W     = (const float*)d_in[2];
    const float* gamma = (const float*)d_in[3];
    const float* beta  = (const float*)d_in[4];
    const float* rmean = (const float*)d_in[5];
    const float* rvar  = (const float*)d_in[6];
    float* out = (float*)d_out;

    k_prep<<<1 + B_ * N_ / 256, 256>>>(coor, W, gamma, beta, rmean, rvar);
    grid_scan<<<1, 128>>>();
    grid_scatter<<<B_ * N_ / 256, 256>>>(coor);
    fgemm_kernel<<<dim3(N_ / 32, B_), 256>>>(fea);
    knn_kernel<<<dim3(N_ / 8, B_), 256>>>(coor);
    agg_kernel<<<dim3(N_ / 4, B_), 128>>>(coor, out);
}

// round 11
// speedup vs baseline: 6.1957x; 1.2942x over previous
#include <cuda_runtime.h>

#define B_ 4
#define C_ 64
#define N_ 8192
#define K_ 32
#define R2_ 0.04f
#define BN_EPS_ 1e-5f
#define NC 5
#define NCELL (NC * NC * NC)
#define INFB 0x7f800000u

typedef unsigned long long ull;

#define FMA2ACC(acc, a, bb) asm("fma.rn.f32x2 %0, %1, %2, %0;" : "+l"(acc) : "l"(a), "l"(bb))

__device__ __forceinline__ ull pack2(float lo, float hi) {
    ull r; asm("mov.b64 %0, {%1, %2};" : "=l"(r) : "f"(lo), "f"(hi)); return r;
}
__device__ __forceinline__ void unpack2(ull v, float& lo, float& hi) {
    asm("mov.b64 {%0, %1}, %2;" : "=f"(lo), "=f"(hi) : "l"(v));
}
__device__ __forceinline__ int cell_clamp(float v) {
    int c = (int)(v * 5.0f);
    return min(NC - 1, max(0, c));
}

// Scratch (static __device__ arrays — no allocation)
__device__ float  g_F[B_ * N_ * C_];      // F[b][n][d] = fea row . W_fea[d] * scale
__device__ int    g_gidx[B_ * N_ * K_];   // final (masked) neighbor indices
__device__ ull    g_WsT2[32 * 64];        // packed (w[2c],w[2c+1]) per d, BN-scaled
__device__ float  g_Wc[3 * 64];           // coord weights * scale
__device__ float  g_bias[64];             // BN-folded bias
// grid structures
__device__ int    g_cnt[B_ * NCELL];      // zeroed by agg (last kernel) for replay
__device__ int    g_cellStart[B_ * (NCELL + 1)];
__device__ int    g_rank[B_ * N_];        // intra-cell rank per point
__device__ float4 g_pts[B_ * N_];         // cell-sorted (x,y,z,sq)
__device__ int    g_pid[B_ * N_];         // original point index

// ---------------------------------------------------------------------------
// K1: W-fold block [0] + grid count blocks [1,129). Count records each
// point's intra-cell rank (atomic return) so scatter needs no atomics.
// Intra-cell order is nondeterministic but the KNN selection key
// (d_bits, idx) is visit-order invariant => output deterministic.
// ---------------------------------------------------------------------------
__global__ __launch_bounds__(256) void k_prep(
    const float* __restrict__ coor,
    const float* __restrict__ W,
    const float* __restrict__ gamma_, const float* __restrict__ beta_,
    const float* __restrict__ rmean, const float* __restrict__ rvar)
{
    const int bid = blockIdx.x;
    const int tid = threadIdx.x;
    if (bid == 0) {
        if (tid < 64) {
            float sc = gamma_[tid] * rsqrtf(rvar[tid] + BN_EPS_);
            g_bias[tid] = beta_[tid] - rmean[tid] * sc;
            g_Wc[tid]       = W[tid * 67 + 64] * sc;
            g_Wc[64 + tid]  = W[tid * 67 + 65] * sc;
            g_Wc[128 + tid] = W[tid * 67 + 66] * sc;
        }
        for (int e = tid; e < 32 * 64; e += 256) {
            int c2 = e >> 6, d = e & 63;
            float sc = gamma_[d] * rsqrtf(rvar[d] + BN_EPS_);
            g_WsT2[e] = pack2(W[d * 67 + 2 * c2] * sc, W[d * 67 + 2 * c2 + 1] * sc);
        }
    } else {
        int id = (bid - 1) * 256 + tid;
        int b = id / N_, n = id % N_;
        const float* cb = coor + b * 3 * N_;
        int cx = cell_clamp(cb[n]);
        int cy = cell_clamp(cb[N_ + n]);
        int cz = cell_clamp(cb[2 * N_ + n]);
        g_rank[id] = atomicAdd(&g_cnt[b * NCELL + (cz * NC + cy) * NC + cx], 1);
    }
}

// ---------------------------------------------------------------------------
// K2 (fused): blocks [0,128) = scatter (with LOCAL prefix scan of the 125
// cell counts — the standalone scan kernel is gone; duplicate identical
// g_cellStart writes across blocks of a batch are benign), blocks
// [128,1152) = F GEMM.
// ---------------------------------------------------------------------------
__global__ __launch_bounds__(256) void scatter_fgemm(
    const float* __restrict__ coor, const float* __restrict__ fea)
{
    __shared__ ull s_wt[32 * 64];                       // fgemm: [c2][d]  16 KB
    __shared__ __align__(16) float sfea[32 * 66];       // fgemm: [n][c] padded
    __shared__ int sPre[NCELL + 1];                     // scatter: local scan
    const int bid = blockIdx.x;
    const int tid = threadIdx.x;

    if (bid < 128) {
        // ---- scatter: 32 blocks per batch, b uniform per block ----
        const int b  = bid >> 5;
        const int id = bid * 256 + tid;
        const int n  = id % N_;
        if (tid < 32) {
            int carry = 0;
            if (tid == 0) sPre[0] = 0;
            for (int c0 = 0; c0 < NCELL; c0 += 32) {
                int i = c0 + tid;
                int v = (i < NCELL) ? g_cnt[b * NCELL + i] : 0;
#pragma unroll
                for (int o = 1; o < 32; o <<= 1) {
                    int tv = __shfl_up_sync(0xffffffffu, v, o);
                    if (tid >= o) v += tv;
                }
                if (i < NCELL) sPre[i + 1] = carry + v;
                carry += __shfl_sync(0xffffffffu, v, 31);
            }
        }
        __syncthreads();
        for (int i = tid; i <= NCELL; i += 256)
            g_cellStart[b * (NCELL + 1) + i] = sPre[i];

        const float* cb = coor + b * 3 * N_;
        float x = cb[n], y = cb[N_ + n], z = cb[2 * N_ + n];
        float sq = fmaf(x, x, fmaf(y, y, z * z));   // same chain as query side
        int cx = cell_clamp(x), cy = cell_clamp(y), cz = cell_clamp(z);
        int pos = sPre[(cz * NC + cy) * NC + cx] + g_rank[id];
        g_pts[b * N_ + pos] = make_float4(x, y, z, sq);
        g_pid[b * N_ + pos] = n;
    } else {
        // ---- F GEMM: warp = 8 d's x 32 n's, 8 outputs/thread ----
        const int fb  = bid - 128;          // [0,1024)
        const int b   = fb >> 8;            // 256 n-chunks per batch
        const int n0  = (fb & 255) * 32;
        const int w   = tid >> 5, lane = tid & 31;

        for (int e = tid; e < 32 * 64; e += 256) s_wt[e] = g_WsT2[e];
#pragma unroll
        for (int i = 0; i < 8; i++) {
            int c = w * 8 + i;
            sfea[lane * 66 + c] = fea[(b * 64 + c) * N_ + n0 + lane];
        }
        __syncthreads();

        const ull* frow = reinterpret_cast<const ull*>(sfea + lane * 66);
        const int d0 = w * 8;
        ull acc[8];
#pragma unroll
        for (int j = 0; j < 8; j++) acc[j] = 0ull;
#pragma unroll 8
        for (int c2 = 0; c2 < 32; c2++) {
            ull f = frow[c2];
            const ull* wr = s_wt + c2 * 64 + d0;
            ulonglong2 w01 = *reinterpret_cast<const ulonglong2*>(wr);
            ulonglong2 w23 = *reinterpret_cast<const ulonglong2*>(wr + 2);
            ulonglong2 w45 = *reinterpret_cast<const ulonglong2*>(wr + 4);
            ulonglong2 w67 = *reinterpret_cast<const ulonglong2*>(wr + 6);
            FMA2ACC(acc[0], f, w01.x); FMA2ACC(acc[1], f, w01.y);
            FMA2ACC(acc[2], f, w23.x); FMA2ACC(acc[3], f, w23.y);
            FMA2ACC(acc[4], f, w45.x); FMA2ACC(acc[5], f, w45.y);
            FMA2ACC(acc[6], f, w67.x); FMA2ACC(acc[7], f, w67.y);
        }
        float o[8];
#pragma unroll
        for (int j = 0; j < 8; j++) {
            float lo, hi; unpack2(acc[j], lo, hi);
            o[j] = lo + hi;
        }
        float4* dst = reinterpret_cast<float4*>(
            g_F + ((size_t)(b * N_ + n0 + lane)) * 64 + d0);
        dst[0] = make_float4(o[0], o[1], o[2], o[3]);
        dst[1] = make_float4(o[4], o[5], o[6], o[7]);
    }
}

// ---------------------------------------------------------------------------
// KNN: one warp per query, distributed top-32 heap keyed on (d_bits, idx)
// (visit-order invariant), nearest-cell-first with provable early exit.
// NEW: heap-FILL phase is batched — while count<32 every in-ball candidate
// qualifies (cmd = +inf), so a whole ballot is slotted at once via a per-warp
// smem stage (popc-rank -> slot). Resulting heap state identical to the
// sequential inserts; eviction loop unchanged.
// ---------------------------------------------------------------------------
__global__ __launch_bounds__(256) void knn_kernel(const float* __restrict__ coor) {
    __shared__ ull s_stage[8][32];

    const int b    = blockIdx.y;
    const int warp = threadIdx.x >> 5;
    const int lane = threadIdx.x & 31;
    const int q    = blockIdx.x * 8 + warp;

    const float* cb = coor + b * 3 * N_;
    const float qx  = cb[q];
    const float qy  = cb[N_ + q];
    const float qz  = cb[2 * N_ + q];
    const float qsq = fmaf(qx, qx, fmaf(qy, qy, qz * qz));

    int s = 0, e = 0;
    unsigned mdu = INFB;
    {
        int qcx = cell_clamp(qx), qcy = cell_clamp(qy), qcz = cell_clamp(qz);
        if (lane < 27) {
            int cx = qcx + (lane % 3) - 1;
            int cy = qcy + ((lane / 3) % 3) - 1;
            int cz = qcz + (lane / 9) - 1;
            if (cx >= 0 && cx < NC && cy >= 0 && cy < NC && cz >= 0 && cz < NC) {
                float bx0 = cx * 0.2f, by0 = cy * 0.2f, bz0 = cz * 0.2f;
                float ddx = fmaxf(0.f, fmaxf(bx0 - qx, qx - (bx0 + 0.2f)));
                float ddy = fmaxf(0.f, fmaxf(by0 - qy, qy - (by0 + 0.2f)));
                float ddz = fmaxf(0.f, fmaxf(bz0 - qz, qz - (bz0 + 0.2f)));
                float md = ddx * ddx + ddy * ddy + ddz * ddz;
                if (md <= R2_ + 1e-5f) {
                    int ci = b * (NCELL + 1) + (cz * NC + cy) * NC + cx;
                    s = g_cellStart[ci];
                    e = g_cellStart[ci + 1];
                    mdu = __float_as_uint(md);
                }
            }
        }
    }

    unsigned mydb  = INFB;
    unsigned myidx = 0u;
    unsigned cmd = INFB, cmi = 0u;
    int maxlane = 0;
    int count = 0;                 // warp-uniform filled slot count

    const float4* pts = g_pts + b * N_;
    const int*    pid = g_pid + b * N_;

#pragma unroll 1
    for (int r = 0; r < 27; r++) {
        unsigned rmin = __reduce_min_sync(0xffffffffu, mdu);
        if (rmin == INFB) break;
        if (count == 32 &&
            __uint_as_float(cmd) + 4e-6f < __uint_as_float(rmin)) break;
        int j = __ffs(__ballot_sync(0xffffffffu, mdu == rmin)) - 1;
        int cs = __shfl_sync(0xffffffffu, s, j);
        int ce = __shfl_sync(0xffffffffu, e, j);
        if (lane == j) mdu = INFB;

        for (int i0 = cs; i0 < ce; i0 += 32) {
            int i = i0 + lane;
            bool act = i < ce;
            float4 p = act ? pts[i]
                           : make_float4(0.f, 0.f, 0.f, __int_as_float(0x7f800000));
            float dot = fmaf(qx, p.x, fmaf(qy, p.y, qz * p.z));
            float d   = fmaf(-2.f, dot, qsq + p.w);
            d = fmaxf(d, 0.f);
            unsigned db = __float_as_uint(d);
            unsigned pv = act ? (unsigned)pid[i] : 0u;
            bool ok = act && (d <= R2_) &&
                      (db < cmd || (db == cmd && pv < cmi));
            unsigned mask = __ballot_sync(0xffffffffu, ok);

            // ---- batched fill (heap not yet full) ----
            if (count < 32 && mask) {
                int m    = __popc(mask);
                int take = min(32 - count, m);
                int rank = __popc(mask & ((1u << lane) - 1u));
                if (ok && rank < take)
                    s_stage[warp][rank] = ((ull)db << 32) | pv;
                __syncwarp();
                int rr = lane - count;
                if (rr >= 0 && rr < take) {
                    ull v = s_stage[warp][rr];
                    mydb  = (unsigned)(v >> 32);
                    myidx = (unsigned)v;
                }
                count += take;
                if (take == m) mask = 0;
                else
                    for (int t = 0; t < take; t++) mask &= mask - 1;
                if (count == 32) {
                    cmd = __reduce_max_sync(0xffffffffu, mydb);
                    bool eq = (mydb == cmd);
                    cmi = __reduce_max_sync(0xffffffffu, eq ? myidx : 0u);
                    maxlane = __ffs(__ballot_sync(0xffffffffu,
                                        eq && (myidx == cmi))) - 1;
                }
            }

            // ---- eviction (heap full), unchanged ----
            while (mask) {
                int jj = __ffs(mask) - 1;
                mask &= mask - 1;
                unsigned djb = __shfl_sync(0xffffffffu, db, jj);
                unsigned cj  = __shfl_sync(0xffffffffu, pv, jj);
                if (djb < cmd || (djb == cmd && cj < cmi)) {
                    if (lane == maxlane) { mydb = djb; myidx = cj; }
                    cmd = __reduce_max_sync(0xffffffffu, mydb);
                    bool eq = (mydb == cmd);
                    cmi = __reduce_max_sync(0xffffffffu, eq ? myidx : 0u);
                    maxlane = __ffs(__ballot_sync(0xffffffffu,
                                        eq && (myidx == cmi))) - 1;
                }
            }
        }
    }
    int finalIdx = (__uint_as_float(mydb) <= R2_) ? (int)myidx : q;
    g_gidx[(b * N_ + q) * K_ + lane] = finalIdx;
}

// ---------------------------------------------------------------------------
// Aggregation: warp = one query (64 d's, 2 per lane via f32x2). Block (0,0)
// also re-zeroes g_cnt for the next graph replay.
// ---------------------------------------------------------------------------
__global__ __launch_bounds__(128) void agg_kernel(const float* __restrict__ coor,
                                                  float* __restrict__ out) {
    __shared__ __align__(16) float4 scc[4 * 32];
    __shared__ float sout[4 * 64];

    const int b    = blockIdx.y;
    const int q0   = blockIdx.x * 4;
    const int tid  = threadIdx.x;
    const int q    = tid >> 5;
    const int lane = tid & 31;
    const float* cb = coor + b * 3 * N_;

    if (blockIdx.x == 0 && b == 0)
        for (int i = tid; i < B_ * NCELL; i += 128) g_cnt[i] = 0;

    {
        int id = g_gidx[(b * N_ + q0 + q) * K_ + lane];
        scc[tid] = make_float4((cb[id] - cb[q0 + q]) * 5.0f,
                               (cb[N_ + id] - cb[N_ + q0 + q]) * 5.0f,
                               (cb[2 * N_ + id] - cb[2 * N_ + q0 + q]) * 5.0f,
                               __int_as_float(id));
    }
    __syncthreads();

    const ull wx2 = reinterpret_cast<const ull*>(g_Wc)[lane];
    const ull wy2 = reinterpret_cast<const ull*>(g_Wc + 64)[lane];
    const ull wz2 = reinterpret_cast<const ull*>(g_Wc + 128)[lane];
    const float2 bb = reinterpret_cast<const float2*>(g_bias)[lane];
    const float* Fb = g_F + (size_t)(b * N_) * 64;

    float m0 = __int_as_float(0xff800000), m1 = m0;
#pragma unroll 4
    for (int k = 0; k < 32; k++) {
        float4 cc = scc[q * 32 + k];
        int id = __float_as_int(cc.w);
        ull y = reinterpret_cast<const ull*>(Fb + id * 64)[lane];
        FMA2ACC(y, pack2(cc.x, cc.x), wx2);
        FMA2ACC(y, pack2(cc.y, cc.y), wy2);
        FMA2ACC(y, pack2(cc.z, cc.z), wz2);
        float y0, y1; unpack2(y, y0, y1);
        m0 = fmaxf(m0, y0);
        m1 = fmaxf(m1, y1);
    }
    sout[q * 64 + 2 * lane]     = fmaxf(m0 + bb.x, 0.f);
    sout[q * 64 + 2 * lane + 1] = fmaxf(m1 + bb.y, 0.f);
    __syncthreads();

    if (tid < 64) {
        float4 v = make_float4(sout[tid], sout[64 + tid],
                               sout[128 + tid], sout[192 + tid]);
        *reinterpret_cast<float4*>(&out[(b * 64 + tid) * N_ + q0]) = v;
    }
}

// ---------------------------------------------------------------------------
extern "C" void kernel_launch(void* const* d_in, const int* in_sizes, int n_in,
                              void* d_out, int out_size) {
    const float* coor  = (const float*)d_in[0];
    const float* fea   = (const float*)d_in[1];
    const float* W     = (const float*)d_in[2];
    const float* gamma = (const float*)d_in[3];
    const float* beta  = (const float*)d_in[4];
    const float* rmean = (const float*)d_in[5];
    const float* rvar  = (const float*)d_in[6];
    float* out = (float*)d_out;

    k_prep<<<1 + B_ * N_ / 256, 256>>>(coor, W, gamma, beta, rmean, rvar);
    scatter_fgemm<<<128 + (N_ / 32) * B_, 256>>>(coor, fea);
    knn_kernel<<<dim3(N_ / 8, B_), 256>>>(coor);
    agg_kernel<<<dim3(N_ / 4, B_), 128>>>(coor, out);
}